// round 1
// baseline (speedup 1.0000x reference)
#include <cuda_runtime.h>
#include <math.h>

#define S_LEN 2048
#define D_MODEL 2048
#define NH 32
#define NKV 8
#define HD 64
#define KV_DIM (NKV * HD)   // 512

// Scratch (no allocations allowed)
__device__ float g_q[S_LEN * D_MODEL];      // 16 MB, post-proj (then post-RoPE) Q: [s][h*64+d]
__device__ float g_k[S_LEN * KV_DIM];       // 4 MB,  post-proj (then post-RoPE) K: [s][kv*64+d]
__device__ float g_v[S_LEN * KV_DIM];       // 4 MB
__device__ float g_attn[S_LEN * D_MODEL];   // 16 MB, attention output [s][h*64+d]

// ---------------------------------------------------------------------------
// Tiled SGEMM: C[M,N] = A[M,K] @ B[K,N], all row-major.
// BM=128, BN=128, BK=8, 256 threads, 8x8 per-thread tile.
// Requires M%128==0, N%128==0, K%8==0 (true for all uses here).
// ---------------------------------------------------------------------------
__global__ __launch_bounds__(256) void sgemm_kernel(
    const float* __restrict__ A, const float* __restrict__ B,
    float* __restrict__ C, int M, int N, int K)
{
    __shared__ float As[8][128];
    __shared__ float Bs[8][128];

    const int bx = blockIdx.x, by = blockIdx.y;
    const int tid = threadIdx.x;
    const int tx = tid % 16;      // 0..15 -> N direction
    const int ty = tid / 16;      // 0..15 -> M direction

    A += (size_t)by * 128 * K;
    B += (size_t)bx * 128;
    C += (size_t)by * 128 * N + (size_t)bx * 128;

    const int aRow  = tid >> 1;         // 0..127
    const int aCol4 = (tid & 1) * 4;    // 0 or 4
    const int bRow  = tid >> 5;         // 0..7
    const int bCol4 = (tid & 31) * 4;   // 0..124

    float acc[8][8];
#pragma unroll
    for (int i = 0; i < 8; i++)
#pragma unroll
        for (int j = 0; j < 8; j++) acc[i][j] = 0.f;

    for (int k0 = 0; k0 < K; k0 += 8) {
        float4 a = *reinterpret_cast<const float4*>(A + (size_t)aRow * K + k0 + aCol4);
        As[aCol4 + 0][aRow] = a.x;
        As[aCol4 + 1][aRow] = a.y;
        As[aCol4 + 2][aRow] = a.z;
        As[aCol4 + 3][aRow] = a.w;
        float4 b = *reinterpret_cast<const float4*>(B + (size_t)(k0 + bRow) * N + bCol4);
        *reinterpret_cast<float4*>(&Bs[bRow][bCol4]) = b;
        __syncthreads();

#pragma unroll
        for (int kk = 0; kk < 8; kk++) {
            float ar[8], br[8];
#pragma unroll
            for (int i = 0; i < 8; i++) ar[i] = As[kk][ty * 8 + i];
#pragma unroll
            for (int j = 0; j < 8; j++) br[j] = Bs[kk][tx * 8 + j];
#pragma unroll
            for (int i = 0; i < 8; i++)
#pragma unroll
                for (int j = 0; j < 8; j++) acc[i][j] += ar[i] * br[j];
        }
        __syncthreads();
    }

#pragma unroll
    for (int i = 0; i < 8; i++) {
#pragma unroll
        for (int j = 0; j < 8; j += 4) {
            float4 v = make_float4(acc[i][j], acc[i][j + 1], acc[i][j + 2], acc[i][j + 3]);
            *reinterpret_cast<float4*>(&C[(size_t)(ty * 8 + i) * N + tx * 8 + j]) = v;
        }
    }
}

// ---------------------------------------------------------------------------
// RoPE applied in place to g_q (S*NH rows) and g_k (S*NKV rows).
// One thread per (row, d) with d in [0,32). cos/sin: [s][64], halves identical.
// ---------------------------------------------------------------------------
__global__ void rope_kernel(const float* __restrict__ cosT, const float* __restrict__ sinT)
{
    int idx = blockIdx.x * blockDim.x + threadIdx.x;
    const int total = S_LEN * (NH + NKV) * (HD / 2);
    if (idx >= total) return;
    int d = idx & 31;
    int row = idx >> 5;
    float* p;
    int s;
    if (row < S_LEN * NH) {
        s = row >> 5;              // /NH
        int h = row & 31;
        p = g_q + (size_t)s * D_MODEL + h * HD;
    } else {
        int r = row - S_LEN * NH;
        s = r >> 3;                // /NKV
        int kv = r & 7;
        p = g_k + (size_t)s * KV_DIM + kv * HD;
    }
    float c = cosT[s * HD + d];
    float sn = sinT[s * HD + d];
    float x1 = p[d];
    float x2 = p[d + 32];
    p[d]      = x1 * c - x2 * sn;
    p[d + 32] = x1 * sn + x2 * c;
}

// ---------------------------------------------------------------------------
// Causal GQA attention, streaming softmax. Grid: (qBlocks=32, heads=32).
// 256 threads: thread t -> row = t/4 (query within 64-block),
// quad = t%4 -> 16-wide slice of both score-columns and O dims.
// Smem: Qs[64*64], Ks[64*65] (reused as P buffer), Vs[64*64] = 49408 B dynamic.
// ---------------------------------------------------------------------------
__global__ __launch_bounds__(256) void attn_kernel()
{
    extern __shared__ float sm[];
    float* Qs = sm;                 // 64*64
    float* Ks = Qs + 64 * 64;       // 64*65 (also P buffer)
    float* Vs = Ks + 64 * 65;       // 64*64

    const int qb = blockIdx.x;
    const int h = blockIdx.y;
    const int kvh = h >> 2;
    const int t = threadIdx.x;
    const int row = t >> 2;
    const int quad = t & 3;
    const int cb = quad * 16;

    // Load & scale Q block
    for (int i = t; i < 64 * 64; i += 256) {
        int r = i >> 6, d = i & 63;
        Qs[i] = g_q[(size_t)(qb * 64 + r) * D_MODEL + h * HD + d] * 0.125f;
    }

    float m = -1e30f, l = 0.f;
    float acc[16];
#pragma unroll
    for (int i = 0; i < 16; i++) acc[i] = 0.f;

    const int qi = qb * 64 + row;

    for (int kt = 0; kt <= qb; kt++) {
        __syncthreads();  // previous tile's P/V reads complete
        for (int i = t; i < 64 * 64; i += 256) {
            int r = i >> 6, d = i & 63;
            size_t src = (size_t)(kt * 64 + r) * KV_DIM + kvh * HD + d;
            Ks[r * 65 + d] = g_k[src];
            Vs[i] = g_v[src];
        }
        __syncthreads();

        // Scores for 16 key-columns
        float sc[16];
#pragma unroll
        for (int j = 0; j < 16; j++) sc[j] = 0.f;
        for (int d = 0; d < 64; d++) {
            float qv = Qs[row * 64 + d];
#pragma unroll
            for (int j = 0; j < 16; j++) sc[j] += qv * Ks[(cb + j) * 65 + d];
        }
#pragma unroll
        for (int j = 0; j < 16; j++)
            if (kt * 64 + cb + j > qi) sc[j] = -1e30f;

        // Row max across quad
        float tmax = sc[0];
#pragma unroll
        for (int j = 1; j < 16; j++) tmax = fmaxf(tmax, sc[j]);
        tmax = fmaxf(tmax, __shfl_xor_sync(0xffffffffu, tmax, 1));
        tmax = fmaxf(tmax, __shfl_xor_sync(0xffffffffu, tmax, 2));
        float newm = fmaxf(m, tmax);
        float escale = expf(m - newm);

        float psum = 0.f;
#pragma unroll
        for (int j = 0; j < 16; j++) {
            sc[j] = expf(sc[j] - newm);
            psum += sc[j];
        }
        psum += __shfl_xor_sync(0xffffffffu, psum, 1);
        psum += __shfl_xor_sync(0xffffffffu, psum, 2);
        l = l * escale + psum;
        m = newm;

        __syncthreads();  // everyone done reading Ks
#pragma unroll
        for (int j = 0; j < 16; j++) Ks[row * 65 + cb + j] = sc[j];
#pragma unroll
        for (int i = 0; i < 16; i++) acc[i] *= escale;
        __syncthreads();  // P ready

        for (int key = 0; key < 64; key++) {
            float pv = Ks[row * 65 + key];
#pragma unroll
            for (int i = 0; i < 16; i++) acc[i] += pv * Vs[key * 64 + cb + i];
        }
    }

    float inv = 1.f / l;
#pragma unroll
    for (int i = 0; i < 16; i++)
        g_attn[(size_t)qi * D_MODEL + h * HD + cb + i] = acc[i] * inv;
}

// ---------------------------------------------------------------------------
extern "C" void kernel_launch(void* const* d_in, const int* in_sizes, int n_in,
                              void* d_out, int out_size)
{
    const float* x    = (const float*)d_in[0];
    const float* cosT = (const float*)d_in[1];
    const float* sinT = (const float*)d_in[2];
    // d_in[3] = mask: unused (causal mask applied analytically; -1e9 underflows to 0)
    const float* wq = (const float*)d_in[4];
    const float* wk = (const float*)d_in[5];
    const float* wv = (const float*)d_in[6];
    const float* wo = (const float*)d_in[7];
    float* out = (float*)d_out;

    float *qp, *kp, *vp, *ap;
    cudaGetSymbolAddress((void**)&qp, g_q);
    cudaGetSymbolAddress((void**)&kp, g_k);
    cudaGetSymbolAddress((void**)&vp, g_v);
    cudaGetSymbolAddress((void**)&ap, g_attn);

    // QKV projections
    sgemm_kernel<<<dim3(D_MODEL / 128, S_LEN / 128), 256>>>(x, wq, qp, S_LEN, D_MODEL, D_MODEL);
    sgemm_kernel<<<dim3(KV_DIM / 128, S_LEN / 128), 256>>>(x, wk, kp, S_LEN, KV_DIM, D_MODEL);
    sgemm_kernel<<<dim3(KV_DIM / 128, S_LEN / 128), 256>>>(x, wv, vp, S_LEN, KV_DIM, D_MODEL);

    // RoPE (in place on g_q, g_k)
    const int ropeTot = S_LEN * (NH + NKV) * (HD / 2);
    rope_kernel<<<(ropeTot + 255) / 256, 256>>>(cosT, sinT);

    // Attention
    const int attnSmem = (64 * 64 + 64 * 65 + 64 * 64) * sizeof(float);  // 49408
    cudaFuncSetAttribute(attn_kernel, cudaFuncAttributeMaxDynamicSharedMemorySize, attnSmem);
    attn_kernel<<<dim3(S_LEN / 64, NH), 256, attnSmem>>>();

    // Output projection
    sgemm_kernel<<<dim3(D_MODEL / 128, S_LEN / 128), 256>>>(ap, wo, out, S_LEN, D_MODEL, D_MODEL);

    // new_k, new_v (post-RoPE K, raw V), concatenated after `out`
    const size_t outElems = (size_t)S_LEN * D_MODEL;           // 4194304
    const size_t kvElems = (size_t)S_LEN * KV_DIM;             // 1048576
    if ((size_t)out_size >= outElems + 2 * kvElems) {
        cudaMemcpyAsync(out + outElems, kp, kvElems * sizeof(float),
                        cudaMemcpyDeviceToDevice);
        cudaMemcpyAsync(out + outElems + kvElems, vp, kvElems * sizeof(float),
                        cudaMemcpyDeviceToDevice);
    }
}

// round 2
// speedup vs baseline: 1.0393x; 1.0393x over previous
#include <cuda_runtime.h>
#include <math.h>

#define S_LEN 2048
#define D_MODEL 2048
#define NH 32
#define NKV 8
#define HD 64
#define KV_DIM (NKV * HD)   // 512

// Scratch (no allocations allowed)
__device__ float g_q[S_LEN * D_MODEL];      // post-proj (then post-RoPE) Q: [s][h*64+d]
__device__ float g_k[S_LEN * KV_DIM];       // post-proj (then post-RoPE) K
__device__ float g_v[S_LEN * KV_DIM];
__device__ float g_attn[S_LEN * D_MODEL];   // attention output [s][h*64+d]

// ---------------------------------------------------------------------------
// tf32 helpers
// ---------------------------------------------------------------------------
__device__ __forceinline__ void split_tf32(float x, unsigned& hi, unsigned& lo)
{
    unsigned h;
    asm("cvt.rna.tf32.f32 %0, %1;" : "=r"(h) : "f"(x));
    float hf = __uint_as_float(h);
    unsigned l;
    asm("cvt.rna.tf32.f32 %0, %1;" : "=r"(l) : "f"(x - hf));
    hi = h; lo = l;
}

__device__ __forceinline__ void mma_tf32(float* c, unsigned a0, unsigned a1,
                                         unsigned a2, unsigned a3,
                                         unsigned b0, unsigned b1)
{
    asm volatile(
        "mma.sync.aligned.m16n8k8.row.col.f32.tf32.tf32.f32 "
        "{%0,%1,%2,%3},{%4,%5,%6,%7},{%8,%9},{%0,%1,%2,%3};\n"
        : "+f"(c[0]), "+f"(c[1]), "+f"(c[2]), "+f"(c[3])
        : "r"(a0), "r"(a1), "r"(a2), "r"(a3), "r"(b0), "r"(b1));
}

// ---------------------------------------------------------------------------
// 3xTF32 tensor-core GEMM: C[M,N] = A[M,K] @ B[K,N], all row-major fp32.
// Block 128x128x16, 8 warps (2M x 4N), warp tile 64x32, mma m16n8k8.
// C = Ah*Bh + Al*Bh + Ah*Bl  (fp32-grade accuracy).
// Requires M%128==0, N%128==0, K%16==0.
// ---------------------------------------------------------------------------
__global__ __launch_bounds__(256) void gemm_tf32_kernel(
    const float* __restrict__ A, const float* __restrict__ B,
    float* __restrict__ C, int M, int N, int K)
{
    __shared__ float As[16][136];   // [k][m], stride 136 -> conflict-free frags
    __shared__ float Bs[16][136];   // [k][n]

    const int tid = threadIdx.x;
    const int lane = tid & 31;
    const int wid = tid >> 5;
    const int wm = wid & 1;         // 0..1  (M)
    const int wn = wid >> 1;        // 0..3  (N)
    const int g = lane >> 2;        // groupID 0..7
    const int q = lane & 3;         // quad lane 0..3

    const int bx = blockIdx.x, by = blockIdx.y;
    A += (size_t)by * 128 * K;
    B += (size_t)bx * 128;
    C += (size_t)by * 128 * N + (size_t)bx * 128;

    const int aRow = tid >> 1;          // 0..127
    const int aCol = (tid & 1) * 8;     // 0 or 8
    const int bRow = tid >> 4;          // 0..15
    const int bCol = (tid & 15) * 8;    // 0..120

    float c[4][4][4];
#pragma unroll
    for (int mt = 0; mt < 4; mt++)
#pragma unroll
        for (int nt = 0; nt < 4; nt++)
#pragma unroll
            for (int i = 0; i < 4; i++) c[mt][nt][i] = 0.f;

    for (int k0 = 0; k0 < K; k0 += 16) {
        // Load A tile 128x16 (transposed into As[k][m])
        float4 a0 = *reinterpret_cast<const float4*>(A + (size_t)aRow * K + k0 + aCol);
        float4 a1 = *reinterpret_cast<const float4*>(A + (size_t)aRow * K + k0 + aCol + 4);
        As[aCol + 0][aRow] = a0.x; As[aCol + 1][aRow] = a0.y;
        As[aCol + 2][aRow] = a0.z; As[aCol + 3][aRow] = a0.w;
        As[aCol + 4][aRow] = a1.x; As[aCol + 5][aRow] = a1.y;
        As[aCol + 6][aRow] = a1.z; As[aCol + 7][aRow] = a1.w;
        // Load B tile 16x128 (natural)
        float4 b0 = *reinterpret_cast<const float4*>(B + (size_t)(k0 + bRow) * N + bCol);
        *reinterpret_cast<float4*>(&Bs[bRow][bCol]) = b0;
        float4 b1 = *reinterpret_cast<const float4*>(B + (size_t)(k0 + bRow) * N + bCol + 4);
        *reinterpret_cast<float4*>(&Bs[bRow][bCol + 4]) = b1;
        __syncthreads();

#pragma unroll
        for (int k8 = 0; k8 < 16; k8 += 8) {
            // A fragments for 4 m-tiles (hi/lo split)
            unsigned ah[4][4], al[4][4];
#pragma unroll
            for (int mt = 0; mt < 4; mt++) {
                int r = wm * 64 + mt * 16 + g;
                float x0 = As[k8 + q][r];
                float x1 = As[k8 + q][r + 8];
                float x2 = As[k8 + q + 4][r];
                float x3 = As[k8 + q + 4][r + 8];
                split_tf32(x0, ah[mt][0], al[mt][0]);
                split_tf32(x1, ah[mt][1], al[mt][1]);
                split_tf32(x2, ah[mt][2], al[mt][2]);
                split_tf32(x3, ah[mt][3], al[mt][3]);
            }
#pragma unroll
            for (int nt = 0; nt < 4; nt++) {
                int col = wn * 32 + nt * 8 + g;
                float y0 = Bs[k8 + q][col];
                float y1 = Bs[k8 + q + 4][col];
                unsigned bh0, bl0, bh1, bl1;
                split_tf32(y0, bh0, bl0);
                split_tf32(y1, bh1, bl1);
#pragma unroll
                for (int mt = 0; mt < 4; mt++) {
                    mma_tf32(c[mt][nt], ah[mt][0], ah[mt][1], ah[mt][2], ah[mt][3], bh0, bh1);
                    mma_tf32(c[mt][nt], al[mt][0], al[mt][1], al[mt][2], al[mt][3], bh0, bh1);
                    mma_tf32(c[mt][nt], ah[mt][0], ah[mt][1], ah[mt][2], ah[mt][3], bl0, bl1);
                }
            }
        }
        __syncthreads();
    }

    // Epilogue: float2 stores (c0,c1 contiguous; c2,c3 contiguous)
#pragma unroll
    for (int mt = 0; mt < 4; mt++) {
#pragma unroll
        for (int nt = 0; nt < 4; nt++) {
            int row = wm * 64 + mt * 16 + g;
            int col = wn * 32 + nt * 8 + q * 2;
            *reinterpret_cast<float2*>(&C[(size_t)row * N + col]) =
                make_float2(c[mt][nt][0], c[mt][nt][1]);
            *reinterpret_cast<float2*>(&C[(size_t)(row + 8) * N + col]) =
                make_float2(c[mt][nt][2], c[mt][nt][3]);
        }
    }
}

// ---------------------------------------------------------------------------
// RoPE applied in place to g_q (S*NH rows) and g_k (S*NKV rows).
// ---------------------------------------------------------------------------
__global__ void rope_kernel(const float* __restrict__ cosT, const float* __restrict__ sinT)
{
    int idx = blockIdx.x * blockDim.x + threadIdx.x;
    const int total = S_LEN * (NH + NKV) * (HD / 2);
    if (idx >= total) return;
    int d = idx & 31;
    int row = idx >> 5;
    float* p;
    int s;
    if (row < S_LEN * NH) {
        s = row >> 5;
        int h = row & 31;
        p = g_q + (size_t)s * D_MODEL + h * HD;
    } else {
        int r = row - S_LEN * NH;
        s = r >> 3;
        int kv = r & 7;
        p = g_k + (size_t)s * KV_DIM + kv * HD;
    }
    float c = cosT[s * HD + d];
    float sn = sinT[s * HD + d];
    float x1 = p[d];
    float x2 = p[d + 32];
    p[d]      = x1 * c - x2 * sn;
    p[d + 32] = x1 * sn + x2 * c;
}

// ---------------------------------------------------------------------------
// Causal GQA attention, streaming softmax. Grid: (qBlocks=32, heads=32).
// ---------------------------------------------------------------------------
__global__ __launch_bounds__(256) void attn_kernel()
{
    extern __shared__ float sm[];
    float* Qs = sm;                 // 64*64
    float* Ks = Qs + 64 * 64;       // 64*65 (also P buffer)
    float* Vs = Ks + 64 * 65;       // 64*64

    const int qb = blockIdx.x;
    const int h = blockIdx.y;
    const int kvh = h >> 2;
    const int t = threadIdx.x;
    const int row = t >> 2;
    const int quad = t & 3;
    const int cb = quad * 16;

    for (int i = t; i < 64 * 64; i += 256) {
        int r = i >> 6, d = i & 63;
        Qs[i] = g_q[(size_t)(qb * 64 + r) * D_MODEL + h * HD + d] * 0.125f;
    }

    float m = -1e30f, l = 0.f;
    float acc[16];
#pragma unroll
    for (int i = 0; i < 16; i++) acc[i] = 0.f;

    const int qi = qb * 64 + row;

    for (int kt = 0; kt <= qb; kt++) {
        __syncthreads();
        for (int i = t; i < 64 * 64; i += 256) {
            int r = i >> 6, d = i & 63;
            size_t src = (size_t)(kt * 64 + r) * KV_DIM + kvh * HD + d;
            Ks[r * 65 + d] = g_k[src];
            Vs[i] = g_v[src];
        }
        __syncthreads();

        float sc[16];
#pragma unroll
        for (int j = 0; j < 16; j++) sc[j] = 0.f;
        for (int d = 0; d < 64; d++) {
            float qv = Qs[row * 64 + d];
#pragma unroll
            for (int j = 0; j < 16; j++) sc[j] += qv * Ks[(cb + j) * 65 + d];
        }
#pragma unroll
        for (int j = 0; j < 16; j++)
            if (kt * 64 + cb + j > qi) sc[j] = -1e30f;

        float tmax = sc[0];
#pragma unroll
        for (int j = 1; j < 16; j++) tmax = fmaxf(tmax, sc[j]);
        tmax = fmaxf(tmax, __shfl_xor_sync(0xffffffffu, tmax, 1));
        tmax = fmaxf(tmax, __shfl_xor_sync(0xffffffffu, tmax, 2));
        float newm = fmaxf(m, tmax);
        float escale = expf(m - newm);

        float psum = 0.f;
#pragma unroll
        for (int j = 0; j < 16; j++) {
            sc[j] = expf(sc[j] - newm);
            psum += sc[j];
        }
        psum += __shfl_xor_sync(0xffffffffu, psum, 1);
        psum += __shfl_xor_sync(0xffffffffu, psum, 2);
        l = l * escale + psum;
        m = newm;

        __syncthreads();
#pragma unroll
        for (int j = 0; j < 16; j++) Ks[row * 65 + cb + j] = sc[j];
#pragma unroll
        for (int i = 0; i < 16; i++) acc[i] *= escale;
        __syncthreads();

        for (int key = 0; key < 64; key++) {
            float pv = Ks[row * 65 + key];
#pragma unroll
            for (int i = 0; i < 16; i++) acc[i] += pv * Vs[key * 64 + cb + i];
        }
    }

    float inv = 1.f / l;
#pragma unroll
    for (int i = 0; i < 16; i++)
        g_attn[(size_t)qi * D_MODEL + h * HD + cb + i] = acc[i] * inv;
}

// ---------------------------------------------------------------------------
extern "C" void kernel_launch(void* const* d_in, const int* in_sizes, int n_in,
                              void* d_out, int out_size)
{
    const float* x    = (const float*)d_in[0];
    const float* cosT = (const float*)d_in[1];
    const float* sinT = (const float*)d_in[2];
    // d_in[3] = mask: causal mask applied analytically
    const float* wq = (const float*)d_in[4];
    const float* wk = (const float*)d_in[5];
    const float* wv = (const float*)d_in[6];
    const float* wo = (const float*)d_in[7];
    float* out = (float*)d_out;

    float *qp, *kp, *vp, *ap;
    cudaGetSymbolAddress((void**)&qp, g_q);
    cudaGetSymbolAddress((void**)&kp, g_k);
    cudaGetSymbolAddress((void**)&vp, g_v);
    cudaGetSymbolAddress((void**)&ap, g_attn);

    // QKV projections (tensor cores, 3xTF32)
    gemm_tf32_kernel<<<dim3(D_MODEL / 128, S_LEN / 128), 256>>>(x, wq, qp, S_LEN, D_MODEL, D_MODEL);
    gemm_tf32_kernel<<<dim3(KV_DIM / 128, S_LEN / 128), 256>>>(x, wk, kp, S_LEN, KV_DIM, D_MODEL);
    gemm_tf32_kernel<<<dim3(KV_DIM / 128, S_LEN / 128), 256>>>(x, wv, vp, S_LEN, KV_DIM, D_MODEL);

    // RoPE (in place on g_q, g_k)
    const int ropeTot = S_LEN * (NH + NKV) * (HD / 2);
    rope_kernel<<<(ropeTot + 255) / 256, 256>>>(cosT, sinT);

    // Attention
    const int attnSmem = (64 * 64 + 64 * 65 + 64 * 64) * sizeof(float);  // 49408
    cudaFuncSetAttribute(attn_kernel, cudaFuncAttributeMaxDynamicSharedMemorySize, attnSmem);
    attn_kernel<<<dim3(S_LEN / 64, NH), 256, attnSmem>>>();

    // Output projection
    gemm_tf32_kernel<<<dim3(D_MODEL / 128, S_LEN / 128), 256>>>(ap, wo, out, S_LEN, D_MODEL, D_MODEL);

    // new_k, new_v (post-RoPE K, raw V)
    const size_t outElems = (size_t)S_LEN * D_MODEL;
    const size_t kvElems = (size_t)S_LEN * KV_DIM;
    if ((size_t)out_size >= outElems + 2 * kvElems) {
        cudaMemcpyAsync(out + outElems, kp, kvElems * sizeof(float),
                        cudaMemcpyDeviceToDevice);
        cudaMemcpyAsync(out + outElems + kvElems, vp, kvElems * sizeof(float),
                        cudaMemcpyDeviceToDevice);
    }
}

// round 3
// speedup vs baseline: 2.4412x; 2.3489x over previous
#include <cuda_runtime.h>
#include <math.h>

#define S_LEN 2048
#define D_MODEL 2048
#define NH 32
#define NKV 8
#define HD 64
#define KV_DIM (NKV * HD)   // 512

// Scratch (no allocations allowed)
__device__ float g_q[S_LEN * D_MODEL];      // post-proj (then post-RoPE) Q: [s][h*64+d]
__device__ float g_k[S_LEN * KV_DIM];       // post-proj (then post-RoPE) K
__device__ float g_v[S_LEN * KV_DIM];
__device__ float g_attn[S_LEN * D_MODEL];   // attention output [s][h*64+d]

// ---------------------------------------------------------------------------
// tf32 helpers
// ---------------------------------------------------------------------------
__device__ __forceinline__ void split_tf32(float x, unsigned& hi, unsigned& lo)
{
    unsigned h;
    asm("cvt.rna.tf32.f32 %0, %1;" : "=r"(h) : "f"(x));
    float hf = __uint_as_float(h);
    unsigned l;
    asm("cvt.rna.tf32.f32 %0, %1;" : "=r"(l) : "f"(x - hf));
    hi = h; lo = l;
}

__device__ __forceinline__ float tf32r(float x)
{
    unsigned u;
    asm("cvt.rna.tf32.f32 %0, %1;" : "=r"(u) : "f"(x));
    return __uint_as_float(u);
}

__device__ __forceinline__ void mma_tf32(float* c, unsigned a0, unsigned a1,
                                         unsigned a2, unsigned a3,
                                         unsigned b0, unsigned b1)
{
    asm volatile(
        "mma.sync.aligned.m16n8k8.row.col.f32.tf32.tf32.f32 "
        "{%0,%1,%2,%3},{%4,%5,%6,%7},{%8,%9},{%0,%1,%2,%3};\n"
        : "+f"(c[0]), "+f"(c[1]), "+f"(c[2]), "+f"(c[3])
        : "r"(a0), "r"(a1), "r"(a2), "r"(a3), "r"(b0), "r"(b1));
}

// ---------------------------------------------------------------------------
// 3xTF32 tensor-core GEMM body: C[M,N] = A[M,K] @ B[K,N], row-major fp32.
// Block 128x128x16, 8 warps (2M x 4N), warp tile 64x32, mma m16n8k8.
// ---------------------------------------------------------------------------
__device__ __forceinline__ void gemm_tf32_body(
    const float* __restrict__ A, const float* __restrict__ B,
    float* __restrict__ C, int N, int K, int bx, int by)
{
    __shared__ float As[16][136];
    __shared__ float Bs[16][136];

    const int tid = threadIdx.x;
    const int lane = tid & 31;
    const int wid = tid >> 5;
    const int wm = wid & 1;
    const int wn = wid >> 1;
    const int g = lane >> 2;
    const int q = lane & 3;

    A += (size_t)by * 128 * K;
    B += (size_t)bx * 128;
    C += (size_t)by * 128 * N + (size_t)bx * 128;

    const int aRow = tid >> 1;
    const int aCol = (tid & 1) * 8;
    const int bRow = tid >> 4;
    const int bCol = (tid & 15) * 8;

    float c[4][4][4];
#pragma unroll
    for (int mt = 0; mt < 4; mt++)
#pragma unroll
        for (int nt = 0; nt < 4; nt++)
#pragma unroll
            for (int i = 0; i < 4; i++) c[mt][nt][i] = 0.f;

    for (int k0 = 0; k0 < K; k0 += 16) {
        float4 a0 = *reinterpret_cast<const float4*>(A + (size_t)aRow * K + k0 + aCol);
        float4 a1 = *reinterpret_cast<const float4*>(A + (size_t)aRow * K + k0 + aCol + 4);
        As[aCol + 0][aRow] = a0.x; As[aCol + 1][aRow] = a0.y;
        As[aCol + 2][aRow] = a0.z; As[aCol + 3][aRow] = a0.w;
        As[aCol + 4][aRow] = a1.x; As[aCol + 5][aRow] = a1.y;
        As[aCol + 6][aRow] = a1.z; As[aCol + 7][aRow] = a1.w;
        float4 b0 = *reinterpret_cast<const float4*>(B + (size_t)(k0 + bRow) * N + bCol);
        *reinterpret_cast<float4*>(&Bs[bRow][bCol]) = b0;
        float4 b1 = *reinterpret_cast<const float4*>(B + (size_t)(k0 + bRow) * N + bCol + 4);
        *reinterpret_cast<float4*>(&Bs[bRow][bCol + 4]) = b1;
        __syncthreads();

#pragma unroll
        for (int k8 = 0; k8 < 16; k8 += 8) {
            unsigned ah[4][4], al[4][4];
#pragma unroll
            for (int mt = 0; mt < 4; mt++) {
                int r = wm * 64 + mt * 16 + g;
                split_tf32(As[k8 + q][r],     ah[mt][0], al[mt][0]);
                split_tf32(As[k8 + q][r + 8], ah[mt][1], al[mt][1]);
                split_tf32(As[k8 + q + 4][r],     ah[mt][2], al[mt][2]);
                split_tf32(As[k8 + q + 4][r + 8], ah[mt][3], al[mt][3]);
            }
#pragma unroll
            for (int nt = 0; nt < 4; nt++) {
                int col = wn * 32 + nt * 8 + g;
                unsigned bh0, bl0, bh1, bl1;
                split_tf32(Bs[k8 + q][col],     bh0, bl0);
                split_tf32(Bs[k8 + q + 4][col], bh1, bl1);
#pragma unroll
                for (int mt = 0; mt < 4; mt++) {
                    mma_tf32(c[mt][nt], ah[mt][0], ah[mt][1], ah[mt][2], ah[mt][3], bh0, bh1);
                    mma_tf32(c[mt][nt], al[mt][0], al[mt][1], al[mt][2], al[mt][3], bh0, bh1);
                    mma_tf32(c[mt][nt], ah[mt][0], ah[mt][1], ah[mt][2], ah[mt][3], bl0, bl1);
                }
            }
        }
        __syncthreads();
    }

#pragma unroll
    for (int mt = 0; mt < 4; mt++) {
#pragma unroll
        for (int nt = 0; nt < 4; nt++) {
            int row = wm * 64 + mt * 16 + g;
            int col = wn * 32 + nt * 8 + q * 2;
            *reinterpret_cast<float2*>(&C[(size_t)row * N + col]) =
                make_float2(c[mt][nt][0], c[mt][nt][1]);
            *reinterpret_cast<float2*>(&C[(size_t)(row + 8) * N + col]) =
                make_float2(c[mt][nt][2], c[mt][nt][3]);
        }
    }
}

// Fused QKV: grid.x = 24 column tiles (16 Q, 4 K, 4 V), grid.y = 16 row tiles.
__global__ __launch_bounds__(256) void qkv_gemm_kernel(
    const float* __restrict__ x, const float* __restrict__ wq,
    const float* __restrict__ wk, const float* __restrict__ wv)
{
    int bx = blockIdx.x;
    const float* B; float* C; int N; int cx;
    if (bx < 16)      { B = wq; C = g_q; N = D_MODEL; cx = bx; }
    else if (bx < 20) { B = wk; C = g_k; N = KV_DIM;  cx = bx - 16; }
    else              { B = wv; C = g_v; N = KV_DIM;  cx = bx - 20; }
    gemm_tf32_body(x, B, C, N, D_MODEL, cx, blockIdx.y);
}

__global__ __launch_bounds__(256) void out_gemm_kernel(
    const float* __restrict__ A, const float* __restrict__ B, float* __restrict__ C)
{
    gemm_tf32_body(A, B, C, D_MODEL, D_MODEL, blockIdx.x, blockIdx.y);
}

// ---------------------------------------------------------------------------
// RoPE applied in place to g_q (S*NH rows) and g_k (S*NKV rows).
// ---------------------------------------------------------------------------
__global__ void rope_kernel(const float* __restrict__ cosT, const float* __restrict__ sinT)
{
    int idx = blockIdx.x * blockDim.x + threadIdx.x;
    const int total = S_LEN * (NH + NKV) * (HD / 2);
    if (idx >= total) return;
    int d = idx & 31;
    int row = idx >> 5;
    float* p;
    int s;
    if (row < S_LEN * NH) {
        s = row >> 5;
        int h = row & 31;
        p = g_q + (size_t)s * D_MODEL + h * HD;
    } else {
        int r = row - S_LEN * NH;
        s = r >> 3;
        int kv = r & 7;
        p = g_k + (size_t)s * KV_DIM + kv * HD;
    }
    float c = cosT[s * HD + d];
    float sn = sinT[s * HD + d];
    float x1 = p[d];
    float x2 = p[d + 32];
    p[d]      = x1 * c - x2 * sn;
    p[d + 32] = x1 * sn + x2 * c;
}

// ---------------------------------------------------------------------------
// Tensor-core causal GQA attention. Grid (qb=32, h=32), 128 threads (4 warps).
// BQ=BK=64. Warp w owns q-rows w*16..w*16+15.
// Smem: Qs[64][76] (reused as Ps), Ks[64][72], Vs[64][72] = 56320 B dynamic.
// Scores: 3xTF32 (fp32-grade). PV: 1xTF32 (P,V tf32-rounded).
// ---------------------------------------------------------------------------
__global__ __launch_bounds__(128, 3) void attn_tc_kernel()
{
    extern __shared__ float sm2[];
    float* Qs = sm2;                 // [64][76]; later reused as Ps (warp-private rows)
    float* Ks = sm2 + 64 * 76;       // [64][72]
    float* Vs = Ks + 64 * 72;        // [64][72]

    const int qb = blockIdx.x, h = blockIdx.y, kvh = h >> 2;
    const int t = threadIdx.x;
    const int lane = t & 31, w = t >> 5;
    const int g = lane >> 2, q = lane & 3;
    const int r0 = w * 16 + g;       // first frag row (also r0+8)

    // Load Q tile (scaled by 1/sqrt(HD))
    for (int i = t; i < 64 * 16; i += 128) {
        int d4 = i & 15, r = i >> 4;
        float4 v = *reinterpret_cast<const float4*>(
            &g_q[(size_t)(qb * 64 + r) * D_MODEL + h * HD + d4 * 4]);
        float* dst = &Qs[r * 76 + d4 * 4];
        dst[0] = v.x * 0.125f; dst[1] = v.y * 0.125f;
        dst[2] = v.z * 0.125f; dst[3] = v.w * 0.125f;
    }
    __syncthreads();

    // Precompute Q fragments (hi/lo split) — loop-invariant across kt.
    unsigned qh[8][4], ql[8][4];
#pragma unroll
    for (int k8 = 0; k8 < 8; k8++) {
        split_tf32(Qs[r0 * 76 + k8 * 8 + q],           qh[k8][0], ql[k8][0]);
        split_tf32(Qs[(r0 + 8) * 76 + k8 * 8 + q],     qh[k8][1], ql[k8][1]);
        split_tf32(Qs[r0 * 76 + k8 * 8 + q + 4],       qh[k8][2], ql[k8][2]);
        split_tf32(Qs[(r0 + 8) * 76 + k8 * 8 + q + 4], qh[k8][3], ql[k8][3]);
    }

    float m0 = -1e30f, m1 = -1e30f, l0 = 0.f, l1 = 0.f;
    float acc[8][4];
#pragma unroll
    for (int nt = 0; nt < 8; nt++)
#pragma unroll
        for (int i = 0; i < 4; i++) acc[nt][i] = 0.f;

    for (int kt = 0; kt <= qb; kt++) {
        __syncthreads();  // previous tile's Ks/Vs reads complete
        for (int i = t; i < 64 * 16; i += 128) {
            int d4 = i & 15, r = i >> 4;
            size_t src = (size_t)(kt * 64 + r) * KV_DIM + kvh * HD + d4 * 4;
            *reinterpret_cast<float4*>(&Ks[r * 72 + d4 * 4]) =
                *reinterpret_cast<const float4*>(&g_k[src]);
            float4 vv = *reinterpret_cast<const float4*>(&g_v[src]);
            vv.x = tf32r(vv.x); vv.y = tf32r(vv.y);
            vv.z = tf32r(vv.z); vv.w = tf32r(vv.w);
            *reinterpret_cast<float4*>(&Vs[r * 72 + d4 * 4]) = vv;
        }
        __syncthreads();

        // Scores: S = Q @ K^T (3xTF32). c[nt] covers keys nt*8..nt*8+7.
        float c[8][4];
#pragma unroll
        for (int nt = 0; nt < 8; nt++)
#pragma unroll
            for (int i = 0; i < 4; i++) c[nt][i] = 0.f;

#pragma unroll
        for (int k8 = 0; k8 < 8; k8++) {
#pragma unroll
            for (int nt = 0; nt < 8; nt++) {
                unsigned bh0, bl0, bh1, bl1;
                split_tf32(Ks[(nt * 8 + g) * 72 + k8 * 8 + q],     bh0, bl0);
                split_tf32(Ks[(nt * 8 + g) * 72 + k8 * 8 + q + 4], bh1, bl1);
                mma_tf32(c[nt], qh[k8][0], qh[k8][1], qh[k8][2], qh[k8][3], bh0, bh1);
                mma_tf32(c[nt], ql[k8][0], ql[k8][1], ql[k8][2], ql[k8][3], bh0, bh1);
                mma_tf32(c[nt], qh[k8][0], qh[k8][1], qh[k8][2], qh[k8][3], bl0, bl1);
            }
        }

        // Causal mask (diagonal tile only)
        if (kt == qb) {
#pragma unroll
            for (int nt = 0; nt < 8; nt++) {
                int k0 = nt * 8 + 2 * q;
                if (k0     > r0)     c[nt][0] = -1e30f;
                if (k0 + 1 > r0)     c[nt][1] = -1e30f;
                if (k0     > r0 + 8) c[nt][2] = -1e30f;
                if (k0 + 1 > r0 + 8) c[nt][3] = -1e30f;
            }
        }

        // Streaming softmax (rows r0 and r0+8)
        float tm0 = -1e30f, tm1 = -1e30f;
#pragma unroll
        for (int nt = 0; nt < 8; nt++) {
            tm0 = fmaxf(tm0, fmaxf(c[nt][0], c[nt][1]));
            tm1 = fmaxf(tm1, fmaxf(c[nt][2], c[nt][3]));
        }
        tm0 = fmaxf(tm0, __shfl_xor_sync(0xffffffffu, tm0, 1));
        tm0 = fmaxf(tm0, __shfl_xor_sync(0xffffffffu, tm0, 2));
        tm1 = fmaxf(tm1, __shfl_xor_sync(0xffffffffu, tm1, 1));
        tm1 = fmaxf(tm1, __shfl_xor_sync(0xffffffffu, tm1, 2));
        float nm0 = fmaxf(m0, tm0), nm1 = fmaxf(m1, tm1);
        float es0 = __expf(m0 - nm0), es1 = __expf(m1 - nm1);

        float ps0 = 0.f, ps1 = 0.f;
#pragma unroll
        for (int nt = 0; nt < 8; nt++) {
            c[nt][0] = __expf(c[nt][0] - nm0);
            c[nt][1] = __expf(c[nt][1] - nm0);
            c[nt][2] = __expf(c[nt][2] - nm1);
            c[nt][3] = __expf(c[nt][3] - nm1);
            ps0 += c[nt][0] + c[nt][1];
            ps1 += c[nt][2] + c[nt][3];
        }
        ps0 += __shfl_xor_sync(0xffffffffu, ps0, 1);
        ps0 += __shfl_xor_sync(0xffffffffu, ps0, 2);
        ps1 += __shfl_xor_sync(0xffffffffu, ps1, 1);
        ps1 += __shfl_xor_sync(0xffffffffu, ps1, 2);
        l0 = l0 * es0 + ps0;
        l1 = l1 * es1 + ps1;
        m0 = nm0; m1 = nm1;

        // Rescale accumulator
#pragma unroll
        for (int nt = 0; nt < 8; nt++) {
            acc[nt][0] *= es0; acc[nt][1] *= es0;
            acc[nt][2] *= es1; acc[nt][3] *= es1;
        }

        // Store P (tf32-rounded) into warp-private rows of Ps (= Qs buffer)
        float* Ps = Qs;
#pragma unroll
        for (int nt = 0; nt < 8; nt++) {
            *reinterpret_cast<float2*>(&Ps[r0 * 76 + nt * 8 + 2 * q]) =
                make_float2(tf32r(c[nt][0]), tf32r(c[nt][1]));
            *reinterpret_cast<float2*>(&Ps[(r0 + 8) * 76 + nt * 8 + 2 * q]) =
                make_float2(tf32r(c[nt][2]), tf32r(c[nt][3]));
        }
        __syncwarp();

        // O += P @ V  (1xTF32)
#pragma unroll
        for (int k8 = 0; k8 < 8; k8++) {
            unsigned pa0 = __float_as_uint(Ps[r0 * 76 + k8 * 8 + q]);
            unsigned pa1 = __float_as_uint(Ps[(r0 + 8) * 76 + k8 * 8 + q]);
            unsigned pa2 = __float_as_uint(Ps[r0 * 76 + k8 * 8 + q + 4]);
            unsigned pa3 = __float_as_uint(Ps[(r0 + 8) * 76 + k8 * 8 + q + 4]);
#pragma unroll
            for (int nt = 0; nt < 8; nt++) {
                unsigned b0 = __float_as_uint(Vs[(k8 * 8 + q) * 72 + nt * 8 + g]);
                unsigned b1 = __float_as_uint(Vs[(k8 * 8 + q + 4) * 72 + nt * 8 + g]);
                mma_tf32(acc[nt], pa0, pa1, pa2, pa3, b0, b1);
            }
        }
    }

    // Epilogue
    float inv0 = 1.f / l0, inv1 = 1.f / l1;
    float* o0 = &g_attn[(size_t)(qb * 64 + r0) * D_MODEL + h * HD];
    float* o1 = &g_attn[(size_t)(qb * 64 + r0 + 8) * D_MODEL + h * HD];
#pragma unroll
    for (int nt = 0; nt < 8; nt++) {
        *reinterpret_cast<float2*>(o0 + nt * 8 + 2 * q) =
            make_float2(acc[nt][0] * inv0, acc[nt][1] * inv0);
        *reinterpret_cast<float2*>(o1 + nt * 8 + 2 * q) =
            make_float2(acc[nt][2] * inv1, acc[nt][3] * inv1);
    }
}

// ---------------------------------------------------------------------------
extern "C" void kernel_launch(void* const* d_in, const int* in_sizes, int n_in,
                              void* d_out, int out_size)
{
    const float* x    = (const float*)d_in[0];
    const float* cosT = (const float*)d_in[1];
    const float* sinT = (const float*)d_in[2];
    // d_in[3] = mask: causal mask applied analytically
    const float* wq = (const float*)d_in[4];
    const float* wk = (const float*)d_in[5];
    const float* wv = (const float*)d_in[6];
    const float* wo = (const float*)d_in[7];
    float* out = (float*)d_out;

    float *qp, *kp, *vp, *ap;
    cudaGetSymbolAddress((void**)&qp, g_q);
    cudaGetSymbolAddress((void**)&kp, g_k);
    cudaGetSymbolAddress((void**)&vp, g_v);
    cudaGetSymbolAddress((void**)&ap, g_attn);

    // Fused QKV projections (tensor cores, 3xTF32)
    qkv_gemm_kernel<<<dim3(24, S_LEN / 128), 256>>>(x, wq, wk, wv);

    // RoPE (in place on g_q, g_k)
    const int ropeTot = S_LEN * (NH + NKV) * (HD / 2);
    rope_kernel<<<(ropeTot + 255) / 256, 256>>>(cosT, sinT);

    // Tensor-core attention
    const int attnSmem = (64 * 76 + 2 * 64 * 72) * sizeof(float);  // 56320
    cudaFuncSetAttribute(attn_tc_kernel, cudaFuncAttributeMaxDynamicSharedMemorySize, attnSmem);
    attn_tc_kernel<<<dim3(S_LEN / 64, NH), 128, attnSmem>>>();

    // Output projection
    out_gemm_kernel<<<dim3(D_MODEL / 128, S_LEN / 128), 256>>>(ap, wo, out);

    // new_k, new_v (post-RoPE K, raw V)
    const size_t outElems = (size_t)S_LEN * D_MODEL;
    const size_t kvElems = (size_t)S_LEN * KV_DIM;
    if ((size_t)out_size >= outElems + 2 * kvElems) {
        cudaMemcpyAsync(out + outElems, kp, kvElems * sizeof(float),
                        cudaMemcpyDeviceToDevice);
        cudaMemcpyAsync(out + outElems + kvElems, vp, kvElems * sizeof(float),
                        cudaMemcpyDeviceToDevice);
    }
}

// round 5
// speedup vs baseline: 5.1685x; 2.1171x over previous
#include <cuda_runtime.h>
#include <cuda_bf16.h>
#include <math.h>

#define S_LEN 2048
#define D_MODEL 2048
#define NH 32
#define NKV 8
#define HD 64
#define KV_DIM (NKV * HD)   // 512

// Scratch (no allocations allowed)
__device__ float g_q[S_LEN * D_MODEL];
__device__ float g_k[S_LEN * KV_DIM];
__device__ float g_v[S_LEN * KV_DIM];
__device__ float g_attn[S_LEN * D_MODEL];

// ---------------------------------------------------------------------------
// bf16 split helpers: x = hi + lo, each bf16 (≈17 effective mantissa bits)
// Packs a k-pair (x0 = k even in low half, x1 = k odd in high half).
// ---------------------------------------------------------------------------
__device__ __forceinline__ void split2(float x0, float x1, unsigned& hi, unsigned& lo)
{
    __nv_bfloat162 h = __floats2bfloat162_rn(x0, x1);
    float h0 = __low2float(h), h1 = __high2float(h);
    __nv_bfloat162 l = __floats2bfloat162_rn(x0 - h0, x1 - h1);
    hi = *reinterpret_cast<unsigned*>(&h);
    lo = *reinterpret_cast<unsigned*>(&l);
}

__device__ __forceinline__ void mma_bf16(float* c, unsigned a0, unsigned a1,
                                         unsigned a2, unsigned a3,
                                         unsigned b0, unsigned b1)
{
    asm volatile(
        "mma.sync.aligned.m16n8k16.row.col.f32.bf16.bf16.f32 "
        "{%0,%1,%2,%3},{%4,%5,%6,%7},{%8,%9},{%0,%1,%2,%3};\n"
        : "+f"(c[0]), "+f"(c[1]), "+f"(c[2]), "+f"(c[3])
        : "r"(a0), "r"(a1), "r"(a2), "r"(a3), "r"(b0), "r"(b1));
}

// ---------------------------------------------------------------------------
// 3xBF16 tensor-core GEMM: C[M,N] = A[M,K] @ B[K,N], row-major fp32.
// Block 128x128x32, 8 warps (2M x 4N), warp tile 64x32, mma m16n8k16.
// Smem: pre-split hi/lo bf16-pair tiles, stride 20 u32 (conflict-free frags).
// ---------------------------------------------------------------------------
#define GST 20

__device__ __forceinline__ void gemm_bf16_body(
    const float* __restrict__ A, const float* __restrict__ B,
    float* __restrict__ C, int N, int K, int bx, int by)
{
    __shared__ unsigned AsH[128 * GST], AsL[128 * GST];
    __shared__ unsigned BsH[128 * GST], BsL[128 * GST];

    const int tid = threadIdx.x;
    const int lane = tid & 31;
    const int wid = tid >> 5;
    const int wm = wid & 1;
    const int wn = wid >> 1;
    const int g = lane >> 2;
    const int q = lane & 3;

    A += (size_t)by * 128 * K;
    B += (size_t)bx * 128;
    C += (size_t)by * 128 * N + (size_t)bx * 128;

    // A stage: thread -> row tid>>1, k half (tid&1)*16, 4 float4 each
    const int aRow = tid >> 1;
    const int aK = (tid & 1) * 16;
    // B stage: warp wid covers kpairs {2*wid, 2*wid+1}; lanes consecutive in n
    const int bN0 = tid & 31;
    const int bP0 = (tid >> 5) * 2;

    float c[4][4][4];
#pragma unroll
    for (int mt = 0; mt < 4; mt++)
#pragma unroll
        for (int nt = 0; nt < 4; nt++)
#pragma unroll
            for (int i = 0; i < 4; i++) c[mt][nt][i] = 0.f;

    for (int k0 = 0; k0 < K; k0 += 32) {
        // ---- stage A (split to bf16 hi/lo pairs) ----
#pragma unroll
        for (int j = 0; j < 4; j++) {
            int k = aK + 4 * j;
            float4 v = *reinterpret_cast<const float4*>(A + (size_t)aRow * K + k0 + k);
            unsigned h0, l0, h1, l1;
            split2(v.x, v.y, h0, l0);
            split2(v.z, v.w, h1, l1);
            AsH[aRow * GST + (k >> 1)] = h0;      AsL[aRow * GST + (k >> 1)] = l0;
            AsH[aRow * GST + (k >> 1) + 1] = h1;  AsL[aRow * GST + (k >> 1) + 1] = l1;
        }
        // ---- stage B (transpose to [n][kpair], split) ----
        // Each (n 0..127, p 0..15) written exactly once: 256 thr x 8 = 2048.
#pragma unroll
        for (int j = 0; j < 8; j++) {
            int n = bN0 + 32 * (j & 3);
            int p = bP0 + (j >> 2);           // p in {2*wid, 2*wid+1} subset of 0..15
            float e0 = B[(size_t)(k0 + 2 * p) * N + n];
            float e1 = B[(size_t)(k0 + 2 * p + 1) * N + n];
            unsigned hh, ll;
            split2(e0, e1, hh, ll);
            BsH[n * GST + p] = hh;  BsL[n * GST + p] = ll;
        }
        __syncthreads();

        // ---- compute: 2 chunks of k16 ----
#pragma unroll
        for (int c8 = 0; c8 < 2; c8++) {
            unsigned ah[4][4], al[4][4];
#pragma unroll
            for (int mt = 0; mt < 4; mt++) {
                int r = wm * 64 + mt * 16 + g;
                ah[mt][0] = AsH[r * GST + c8 * 8 + q];
                ah[mt][1] = AsH[(r + 8) * GST + c8 * 8 + q];
                ah[mt][2] = AsH[r * GST + c8 * 8 + q + 4];
                ah[mt][3] = AsH[(r + 8) * GST + c8 * 8 + q + 4];
                al[mt][0] = AsL[r * GST + c8 * 8 + q];
                al[mt][1] = AsL[(r + 8) * GST + c8 * 8 + q];
                al[mt][2] = AsL[r * GST + c8 * 8 + q + 4];
                al[mt][3] = AsL[(r + 8) * GST + c8 * 8 + q + 4];
            }
#pragma unroll
            for (int nt = 0; nt < 4; nt++) {
                int col = wn * 32 + nt * 8 + g;
                unsigned bh0 = BsH[col * GST + c8 * 8 + q];
                unsigned bh1 = BsH[col * GST + c8 * 8 + q + 4];
                unsigned bl0 = BsL[col * GST + c8 * 8 + q];
                unsigned bl1 = BsL[col * GST + c8 * 8 + q + 4];
#pragma unroll
                for (int mt = 0; mt < 4; mt++) {
                    mma_bf16(c[mt][nt], ah[mt][0], ah[mt][1], ah[mt][2], ah[mt][3], bh0, bh1);
                    mma_bf16(c[mt][nt], al[mt][0], al[mt][1], al[mt][2], al[mt][3], bh0, bh1);
                    mma_bf16(c[mt][nt], ah[mt][0], ah[mt][1], ah[mt][2], ah[mt][3], bl0, bl1);
                }
            }
        }
        __syncthreads();
    }

#pragma unroll
    for (int mt = 0; mt < 4; mt++) {
#pragma unroll
        for (int nt = 0; nt < 4; nt++) {
            int row = wm * 64 + mt * 16 + g;
            int col = wn * 32 + nt * 8 + q * 2;
            *reinterpret_cast<float2*>(&C[(size_t)row * N + col]) =
                make_float2(c[mt][nt][0], c[mt][nt][1]);
            *reinterpret_cast<float2*>(&C[(size_t)(row + 8) * N + col]) =
                make_float2(c[mt][nt][2], c[mt][nt][3]);
        }
    }
}

__global__ __launch_bounds__(256) void qkv_gemm_kernel(
    const float* __restrict__ x, const float* __restrict__ wq,
    const float* __restrict__ wk, const float* __restrict__ wv)
{
    int bx = blockIdx.x;
    const float* B; float* C; int N; int cx;
    if (bx < 16)      { B = wq; C = g_q; N = D_MODEL; cx = bx; }
    else if (bx < 20) { B = wk; C = g_k; N = KV_DIM;  cx = bx - 16; }
    else              { B = wv; C = g_v; N = KV_DIM;  cx = bx - 20; }
    gemm_bf16_body(x, B, C, N, D_MODEL, cx, blockIdx.y);
}

__global__ __launch_bounds__(256) void out_gemm_kernel(
    const float* __restrict__ A, const float* __restrict__ B, float* __restrict__ C)
{
    gemm_bf16_body(A, B, C, D_MODEL, D_MODEL, blockIdx.x, blockIdx.y);
}

// ---------------------------------------------------------------------------
// RoPE in place on g_q, g_k.
// ---------------------------------------------------------------------------
__global__ void rope_kernel(const float* __restrict__ cosT, const float* __restrict__ sinT)
{
    int idx = blockIdx.x * blockDim.x + threadIdx.x;
    const int total = S_LEN * (NH + NKV) * (HD / 2);
    if (idx >= total) return;
    int d = idx & 31;
    int row = idx >> 5;
    float* p;
    int s;
    if (row < S_LEN * NH) {
        s = row >> 5;
        int h = row & 31;
        p = g_q + (size_t)s * D_MODEL + h * HD;
    } else {
        int r = row - S_LEN * NH;
        s = r >> 3;
        int kv = r & 7;
        p = g_k + (size_t)s * KV_DIM + kv * HD;
    }
    float c = cosT[s * HD + d];
    float sn = sinT[s * HD + d];
    float x1 = p[d];
    float x2 = p[d + 32];
    p[d]      = x1 * c - x2 * sn;
    p[d + 32] = x1 * sn + x2 * c;
}

// ---------------------------------------------------------------------------
// Tensor-core causal GQA attention (3xBF16 scores, 3xBF16 PV).
// Grid (qb=32, h=32), 128 threads (4 warps), warp owns 16 q-rows.
// Smem (dynamic): QP (Q then P) hi/lo, Ks hi/lo, Vt hi/lo — [64][36] u32 each.
// ---------------------------------------------------------------------------
#define AST 36

__global__ __launch_bounds__(128, 3) void attn_tc_kernel()
{
    extern __shared__ unsigned smA[];
    unsigned* QPH = smA;
    unsigned* QPL = QPH + 64 * AST;
    unsigned* KsH = QPL + 64 * AST;
    unsigned* KsL = KsH + 64 * AST;
    unsigned* VtH = KsL + 64 * AST;   // [d][keypair]
    unsigned* VtL = VtH + 64 * AST;

    const int qb = blockIdx.x, h = blockIdx.y, kvh = h >> 2;
    const int t = threadIdx.x;
    const int lane = t & 31, w = t >> 5;
    const int g = lane >> 2, q = lane & 3;
    const int r0 = w * 16 + g;

    // V-transpose assignment: fixed d per thread, keypairs over j
    const int vD = t & 63;
    const int vR = t >> 6;

    // ---- stage Q (scaled), split ----
#pragma unroll
    for (int j = 0; j < 8; j++) {
        int i = t + 128 * j;
        int r = i >> 4, d4 = i & 15;
        float4 v = *reinterpret_cast<const float4*>(
            &g_q[(size_t)(qb * 64 + r) * D_MODEL + h * HD + d4 * 4]);
        unsigned h0, l0, h1, l1;
        split2(v.x * 0.125f, v.y * 0.125f, h0, l0);
        split2(v.z * 0.125f, v.w * 0.125f, h1, l1);
        QPH[r * AST + d4 * 2] = h0;      QPL[r * AST + d4 * 2] = l0;
        QPH[r * AST + d4 * 2 + 1] = h1;  QPL[r * AST + d4 * 2 + 1] = l1;
    }
    __syncthreads();

    // ---- preload Q fragments (warp-own rows) ----
    unsigned qh[4][4], ql[4][4];
#pragma unroll
    for (int c8 = 0; c8 < 4; c8++) {
        qh[c8][0] = QPH[r0 * AST + c8 * 8 + q];
        qh[c8][1] = QPH[(r0 + 8) * AST + c8 * 8 + q];
        qh[c8][2] = QPH[r0 * AST + c8 * 8 + q + 4];
        qh[c8][3] = QPH[(r0 + 8) * AST + c8 * 8 + q + 4];
        ql[c8][0] = QPL[r0 * AST + c8 * 8 + q];
        ql[c8][1] = QPL[(r0 + 8) * AST + c8 * 8 + q];
        ql[c8][2] = QPL[r0 * AST + c8 * 8 + q + 4];
        ql[c8][3] = QPL[(r0 + 8) * AST + c8 * 8 + q + 4];
    }

    float m0 = -1e30f, m1 = -1e30f, l0s = 0.f, l1s = 0.f;
    float acc[8][4];
#pragma unroll
    for (int nt = 0; nt < 8; nt++)
#pragma unroll
        for (int i = 0; i < 4; i++) acc[nt][i] = 0.f;

    for (int kt = 0; kt <= qb; kt++) {
        __syncthreads();
        // ---- stage K (natural) ----
#pragma unroll
        for (int j = 0; j < 8; j++) {
            int i = t + 128 * j;
            int r = i >> 4, d4 = i & 15;
            float4 v = *reinterpret_cast<const float4*>(
                &g_k[(size_t)(kt * 64 + r) * KV_DIM + kvh * HD + d4 * 4]);
            unsigned h0, l0, h1, l1;
            split2(v.x, v.y, h0, l0);
            split2(v.z, v.w, h1, l1);
            KsH[r * AST + d4 * 2] = h0;      KsL[r * AST + d4 * 2] = l0;
            KsH[r * AST + d4 * 2 + 1] = h1;  KsL[r * AST + d4 * 2 + 1] = l1;
        }
        // ---- stage V transposed: Vt[d][keypair] ----
#pragma unroll
        for (int j = 0; j < 16; j++) {
            int kp = vR + 2 * j;     // keypair 0..31
            float e0 = g_v[(size_t)(kt * 64 + 2 * kp) * KV_DIM + kvh * HD + vD];
            float e1 = g_v[(size_t)(kt * 64 + 2 * kp + 1) * KV_DIM + kvh * HD + vD];
            unsigned hh, ll;
            split2(e0, e1, hh, ll);
            VtH[vD * AST + kp] = hh;  VtL[vD * AST + kp] = ll;
        }
        __syncthreads();

        // ---- scores S = Q K^T (3xBF16) ----
        float c[8][4];
#pragma unroll
        for (int nt = 0; nt < 8; nt++)
#pragma unroll
            for (int i = 0; i < 4; i++) c[nt][i] = 0.f;

#pragma unroll
        for (int c8 = 0; c8 < 4; c8++) {
#pragma unroll
            for (int nt = 0; nt < 8; nt++) {
                int col = nt * 8 + g;
                unsigned bh0 = KsH[col * AST + c8 * 8 + q];
                unsigned bh1 = KsH[col * AST + c8 * 8 + q + 4];
                unsigned bl0 = KsL[col * AST + c8 * 8 + q];
                unsigned bl1 = KsL[col * AST + c8 * 8 + q + 4];
                mma_bf16(c[nt], qh[c8][0], qh[c8][1], qh[c8][2], qh[c8][3], bh0, bh1);
                mma_bf16(c[nt], ql[c8][0], ql[c8][1], ql[c8][2], ql[c8][3], bh0, bh1);
                mma_bf16(c[nt], qh[c8][0], qh[c8][1], qh[c8][2], qh[c8][3], bl0, bl1);
            }
        }

        // ---- causal mask (diagonal tile) ----
        if (kt == qb) {
#pragma unroll
            for (int nt = 0; nt < 8; nt++) {
                int k0c = nt * 8 + 2 * q;
                if (k0c     > r0)     c[nt][0] = -1e30f;
                if (k0c + 1 > r0)     c[nt][1] = -1e30f;
                if (k0c     > r0 + 8) c[nt][2] = -1e30f;
                if (k0c + 1 > r0 + 8) c[nt][3] = -1e30f;
            }
        }

        // ---- streaming softmax ----
        float tm0 = -1e30f, tm1 = -1e30f;
#pragma unroll
        for (int nt = 0; nt < 8; nt++) {
            tm0 = fmaxf(tm0, fmaxf(c[nt][0], c[nt][1]));
            tm1 = fmaxf(tm1, fmaxf(c[nt][2], c[nt][3]));
        }
        tm0 = fmaxf(tm0, __shfl_xor_sync(0xffffffffu, tm0, 1));
        tm0 = fmaxf(tm0, __shfl_xor_sync(0xffffffffu, tm0, 2));
        tm1 = fmaxf(tm1, __shfl_xor_sync(0xffffffffu, tm1, 1));
        tm1 = fmaxf(tm1, __shfl_xor_sync(0xffffffffu, tm1, 2));
        float nm0 = fmaxf(m0, tm0), nm1 = fmaxf(m1, tm1);
        float es0 = __expf(m0 - nm0), es1 = __expf(m1 - nm1);

        float ps0 = 0.f, ps1 = 0.f;
#pragma unroll
        for (int nt = 0; nt < 8; nt++) {
            c[nt][0] = __expf(c[nt][0] - nm0);
            c[nt][1] = __expf(c[nt][1] - nm0);
            c[nt][2] = __expf(c[nt][2] - nm1);
            c[nt][3] = __expf(c[nt][3] - nm1);
            ps0 += c[nt][0] + c[nt][1];
            ps1 += c[nt][2] + c[nt][3];
        }
        ps0 += __shfl_xor_sync(0xffffffffu, ps0, 1);
        ps0 += __shfl_xor_sync(0xffffffffu, ps0, 2);
        ps1 += __shfl_xor_sync(0xffffffffu, ps1, 1);
        ps1 += __shfl_xor_sync(0xffffffffu, ps1, 2);
        l0s = l0s * es0 + ps0;
        l1s = l1s * es1 + ps1;
        m0 = nm0; m1 = nm1;

#pragma unroll
        for (int nt = 0; nt < 8; nt++) {
            acc[nt][0] *= es0; acc[nt][1] *= es0;
            acc[nt][2] *= es1; acc[nt][3] *= es1;
        }

        // ---- store P (split) into warp-own rows of QP buffers ----
        // c[nt][0],c[nt][1] = keys nt*8+2q, nt*8+2q+1 -> pair index nt*4+q
#pragma unroll
        for (int nt = 0; nt < 8; nt++) {
            unsigned hh, ll;
            split2(c[nt][0], c[nt][1], hh, ll);
            QPH[r0 * AST + nt * 4 + q] = hh;  QPL[r0 * AST + nt * 4 + q] = ll;
            split2(c[nt][2], c[nt][3], hh, ll);
            QPH[(r0 + 8) * AST + nt * 4 + q] = hh;  QPL[(r0 + 8) * AST + nt * 4 + q] = ll;
        }
        __syncwarp();

        // ---- O += P V (3xBF16) ----
#pragma unroll
        for (int c8 = 0; c8 < 4; c8++) {
            unsigned pa0h = QPH[r0 * AST + c8 * 8 + q];
            unsigned pa1h = QPH[(r0 + 8) * AST + c8 * 8 + q];
            unsigned pa2h = QPH[r0 * AST + c8 * 8 + q + 4];
            unsigned pa3h = QPH[(r0 + 8) * AST + c8 * 8 + q + 4];
            unsigned pa0l = QPL[r0 * AST + c8 * 8 + q];
            unsigned pa1l = QPL[(r0 + 8) * AST + c8 * 8 + q];
            unsigned pa2l = QPL[r0 * AST + c8 * 8 + q + 4];
            unsigned pa3l = QPL[(r0 + 8) * AST + c8 * 8 + q + 4];
#pragma unroll
            for (int nt = 0; nt < 8; nt++) {
                int col = nt * 8 + g;
                unsigned bh0 = VtH[col * AST + c8 * 8 + q];
                unsigned bh1 = VtH[col * AST + c8 * 8 + q + 4];
                unsigned bl0 = VtL[col * AST + c8 * 8 + q];
                unsigned bl1 = VtL[col * AST + c8 * 8 + q + 4];
                mma_bf16(acc[nt], pa0h, pa1h, pa2h, pa3h, bh0, bh1);
                mma_bf16(acc[nt], pa0l, pa1l, pa2l, pa3l, bh0, bh1);
                mma_bf16(acc[nt], pa0h, pa1h, pa2h, pa3h, bl0, bl1);
            }
        }
    }

    // ---- epilogue ----
    float inv0 = 1.f / l0s, inv1 = 1.f / l1s;
    float* o0 = &g_attn[(size_t)(qb * 64 + r0) * D_MODEL + h * HD];
    float* o1 = &g_attn[(size_t)(qb * 64 + r0 + 8) * D_MODEL + h * HD];
#pragma unroll
    for (int nt = 0; nt < 8; nt++) {
        *reinterpret_cast<float2*>(o0 + nt * 8 + 2 * q) =
            make_float2(acc[nt][0] * inv0, acc[nt][1] * inv0);
        *reinterpret_cast<float2*>(o1 + nt * 8 + 2 * q) =
            make_float2(acc[nt][2] * inv1, acc[nt][3] * inv1);
    }
}

// ---------------------------------------------------------------------------
extern "C" void kernel_launch(void* const* d_in, const int* in_sizes, int n_in,
                              void* d_out, int out_size)
{
    const float* x    = (const float*)d_in[0];
    const float* cosT = (const float*)d_in[1];
    const float* sinT = (const float*)d_in[2];
    // d_in[3] = mask: causal, applied analytically
    const float* wq = (const float*)d_in[4];
    const float* wk = (const float*)d_in[5];
    const float* wv = (const float*)d_in[6];
    const float* wo = (const float*)d_in[7];
    float* out = (float*)d_out;

    float *qp, *kp, *vp, *ap;
    cudaGetSymbolAddress((void**)&qp, g_q);
    cudaGetSymbolAddress((void**)&kp, g_k);
    cudaGetSymbolAddress((void**)&vp, g_v);
    cudaGetSymbolAddress((void**)&ap, g_attn);

    qkv_gemm_kernel<<<dim3(24, S_LEN / 128), 256>>>(x, wq, wk, wv);

    const int ropeTot = S_LEN * (NH + NKV) * (HD / 2);
    rope_kernel<<<(ropeTot + 255) / 256, 256>>>(cosT, sinT);

    const int attnSmem = 6 * 64 * AST * sizeof(unsigned);   // 55296
    cudaFuncSetAttribute(attn_tc_kernel, cudaFuncAttributeMaxDynamicSharedMemorySize, attnSmem);
    attn_tc_kernel<<<dim3(S_LEN / 64, NH), 128, attnSmem>>>();

    out_gemm_kernel<<<dim3(D_MODEL / 128, S_LEN / 128), 256>>>(ap, wo, out);

    const size_t outElems = (size_t)S_LEN * D_MODEL;
    const size_t kvElems = (size_t)S_LEN * KV_DIM;
    if ((size_t)out_size >= outElems + 2 * kvElems) {
        cudaMemcpyAsync(out + outElems, kp, kvElems * sizeof(float),
                        cudaMemcpyDeviceToDevice);
        cudaMemcpyAsync(out + outElems + kvElems, vp, kvElems * sizeof(float),
                        cudaMemcpyDeviceToDevice);
    }
}

// round 12
// speedup vs baseline: 6.2055x; 1.2007x over previous
#include <cuda_runtime.h>
#include <cuda_bf16.h>
#include <math.h>
#include <stdint.h>

#define S_LEN 2048
#define D_MODEL 2048
#define NH 32
#define NKV 8
#define HD 64
#define KV_DIM (NKV * HD)   // 512

// Scratch (no allocations allowed)
__device__ float g_q[S_LEN * D_MODEL];
__device__ float g_k[S_LEN * KV_DIM];
__device__ float g_v[S_LEN * KV_DIM];
__device__ float g_attn[S_LEN * D_MODEL];

// ---------------------------------------------------------------------------
// bf16 split helpers: x = hi + lo (≈17 effective mantissa bits).
// Packs a k-pair (x0 = k even in low half, x1 = k odd in high half).
// ---------------------------------------------------------------------------
__device__ __forceinline__ void split2(float x0, float x1, unsigned& hi, unsigned& lo)
{
    __nv_bfloat162 h = __floats2bfloat162_rn(x0, x1);
    float h0 = __low2float(h), h1 = __high2float(h);
    __nv_bfloat162 l = __floats2bfloat162_rn(x0 - h0, x1 - h1);
    hi = *reinterpret_cast<unsigned*>(&h);
    lo = *reinterpret_cast<unsigned*>(&l);
}

__device__ __forceinline__ void mma_bf16(float* c, unsigned a0, unsigned a1,
                                         unsigned a2, unsigned a3,
                                         unsigned b0, unsigned b1)
{
    asm volatile(
        "mma.sync.aligned.m16n8k16.row.col.f32.bf16.bf16.f32 "
        "{%0,%1,%2,%3},{%4,%5,%6,%7},{%8,%9},{%0,%1,%2,%3};\n"
        : "+f"(c[0]), "+f"(c[1]), "+f"(c[2]), "+f"(c[3])
        : "r"(a0), "r"(a1), "r"(a2), "r"(a3), "r"(b0), "r"(b1));
}

__device__ __forceinline__ uint32_t smem_u32(const void* p)
{
    uint32_t a;
    asm("{ .reg .u64 t; cvta.to.shared.u64 t, %1; cvt.u32.u64 %0, t; }"
        : "=r"(a) : "l"(p));
    return a;
}

__device__ __forceinline__ void ldsm4(unsigned& r0, unsigned& r1,
                                      unsigned& r2, unsigned& r3, uint32_t addr)
{
    asm volatile("ldmatrix.sync.aligned.m8n8.x4.shared.b16 {%0,%1,%2,%3}, [%4];"
                 : "=r"(r0), "=r"(r1), "=r"(r2), "=r"(r3) : "r"(addr));
}

// ---------------------------------------------------------------------------
// 3xBF16 tensor-core GEMM: C[M,N] = A[M,K] @ B[K,N], row-major fp32.
// Block 128x128x32, 8 warps (2M x 4N), warp tile 64x32, mma m16n8k16.
// Smem: pre-split hi/lo bf16-pair tiles, stride 20 u32. Fragments via ldmatrix.
// ---------------------------------------------------------------------------
#define GST 20

__device__ __forceinline__ void gemm_bf16_body(
    const float* __restrict__ A, const float* __restrict__ B,
    float* __restrict__ C, int N, int K, int bx, int by)
{
    __shared__ unsigned AsH[128 * GST], AsL[128 * GST];
    __shared__ unsigned BsH[128 * GST], BsL[128 * GST];

    const int tid = threadIdx.x;
    const int lane = tid & 31;
    const int wid = tid >> 5;
    const int wm = wid & 1;
    const int wn = wid >> 1;
    const int g = lane >> 2;
    const int q = lane & 3;

    A += (size_t)by * 128 * K;
    B += (size_t)bx * 128;
    C += (size_t)by * 128 * N + (size_t)bx * 128;

    const int aRow = tid >> 1;
    const int aK = (tid & 1) * 16;
    const int bN0 = tid & 31;
    const int bP0 = (tid >> 5) * 2;

    // ldmatrix lane addressing
    const int sel = lane >> 3, rin = lane & 7;
    const uint32_t aHb = smem_u32(AsH), aLb = smem_u32(AsL);
    const uint32_t bHb = smem_u32(BsH), bLb = smem_u32(BsL);
    uint32_t aOff[4];
#pragma unroll
    for (int mt = 0; mt < 4; mt++)
        aOff[mt] = (uint32_t)((wm * 64 + mt * 16 + (sel & 1) * 8 + rin) * GST * 4
                              + (sel >> 1) * 16);
    uint32_t bOff[2];
#pragma unroll
    for (int np = 0; np < 2; np++)
        bOff[np] = (uint32_t)((wn * 32 + np * 16 + (sel >> 1) * 8 + rin) * GST * 4
                              + (sel & 1) * 16);

    float c[4][4][4];
#pragma unroll
    for (int mt = 0; mt < 4; mt++)
#pragma unroll
        for (int nt = 0; nt < 4; nt++)
#pragma unroll
            for (int i = 0; i < 4; i++) c[mt][nt][i] = 0.f;

    for (int k0 = 0; k0 < K; k0 += 32) {
        // ---- stage A (split to bf16 hi/lo pairs) ----
#pragma unroll
        for (int j = 0; j < 4; j++) {
            int k = aK + 4 * j;
            float4 v = *reinterpret_cast<const float4*>(A + (size_t)aRow * K + k0 + k);
            unsigned h0, l0, h1, l1;
            split2(v.x, v.y, h0, l0);
            split2(v.z, v.w, h1, l1);
            AsH[aRow * GST + (k >> 1)] = h0;      AsL[aRow * GST + (k >> 1)] = l0;
            AsH[aRow * GST + (k >> 1) + 1] = h1;  AsL[aRow * GST + (k >> 1) + 1] = l1;
        }
        // ---- stage B (transpose to [n][kpair], split) ----
#pragma unroll
        for (int j = 0; j < 8; j++) {
            int n = bN0 + 32 * (j & 3);
            int p = bP0 + (j >> 2);
            float e0 = B[(size_t)(k0 + 2 * p) * N + n];
            float e1 = B[(size_t)(k0 + 2 * p + 1) * N + n];
            unsigned hh, ll;
            split2(e0, e1, hh, ll);
            BsH[n * GST + p] = hh;  BsL[n * GST + p] = ll;
        }
        __syncthreads();

#pragma unroll
        for (int c8 = 0; c8 < 2; c8++) {
            const uint32_t kB = c8 * 32;
            unsigned ah[4][4], al[4][4];
#pragma unroll
            for (int mt = 0; mt < 4; mt++) {
                ldsm4(ah[mt][0], ah[mt][1], ah[mt][2], ah[mt][3], aHb + aOff[mt] + kB);
                ldsm4(al[mt][0], al[mt][1], al[mt][2], al[mt][3], aLb + aOff[mt] + kB);
            }
#pragma unroll
            for (int np = 0; np < 2; np++) {
                unsigned bh[4], bl[4];
                ldsm4(bh[0], bh[1], bh[2], bh[3], bHb + bOff[np] + kB);
                ldsm4(bl[0], bl[1], bl[2], bl[3], bLb + bOff[np] + kB);
#pragma unroll
                for (int sub = 0; sub < 2; sub++) {
                    int nt = np * 2 + sub;
#pragma unroll
                    for (int mt = 0; mt < 4; mt++) {
                        mma_bf16(c[mt][nt], ah[mt][0], ah[mt][1], ah[mt][2], ah[mt][3],
                                 bh[sub * 2], bh[sub * 2 + 1]);
                        mma_bf16(c[mt][nt], al[mt][0], al[mt][1], al[mt][2], al[mt][3],
                                 bh[sub * 2], bh[sub * 2 + 1]);
                        mma_bf16(c[mt][nt], ah[mt][0], ah[mt][1], ah[mt][2], ah[mt][3],
                                 bl[sub * 2], bl[sub * 2 + 1]);
                    }
                }
            }
        }
        __syncthreads();
    }

#pragma unroll
    for (int mt = 0; mt < 4; mt++) {
#pragma unroll
        for (int nt = 0; nt < 4; nt++) {
            int row = wm * 64 + mt * 16 + g;
            int col = wn * 32 + nt * 8 + q * 2;
            *reinterpret_cast<float2*>(&C[(size_t)row * N + col]) =
                make_float2(c[mt][nt][0], c[mt][nt][1]);
            *reinterpret_cast<float2*>(&C[(size_t)(row + 8) * N + col]) =
                make_float2(c[mt][nt][2], c[mt][nt][3]);
        }
    }
}

__global__ __launch_bounds__(256) void qkv_gemm_kernel(
    const float* __restrict__ x, const float* __restrict__ wq,
    const float* __restrict__ wk, const float* __restrict__ wv)
{
    int bx = blockIdx.x;
    const float* B; float* C; int N; int cx;
    if (bx < 16)      { B = wq; C = g_q; N = D_MODEL; cx = bx; }
    else if (bx < 20) { B = wk; C = g_k; N = KV_DIM;  cx = bx - 16; }
    else              { B = wv; C = g_v; N = KV_DIM;  cx = bx - 20; }
    gemm_bf16_body(x, B, C, N, D_MODEL, cx, blockIdx.y);
}

__global__ __launch_bounds__(256) void out_gemm_kernel(
    const float* __restrict__ A, const float* __restrict__ B, float* __restrict__ C)
{
    gemm_bf16_body(A, B, C, D_MODEL, D_MODEL, blockIdx.x, blockIdx.y);
}

// ---------------------------------------------------------------------------
// RoPE in place on g_q, g_k.
// ---------------------------------------------------------------------------
__global__ void rope_kernel(const float* __restrict__ cosT, const float* __restrict__ sinT)
{
    int idx = blockIdx.x * blockDim.x + threadIdx.x;
    const int total = S_LEN * (NH + NKV) * (HD / 2);
    if (idx >= total) return;
    int d = idx & 31;
    int row = idx >> 5;
    float* p;
    int s;
    if (row < S_LEN * NH) {
        s = row >> 5;
        int h = row & 31;
        p = g_q + (size_t)s * D_MODEL + h * HD;
    } else {
        int r = row - S_LEN * NH;
        s = r >> 3;
        int kv = r & 7;
        p = g_k + (size_t)s * KV_DIM + kv * HD;
    }
    float c = cosT[s * HD + d];
    float sn = sinT[s * HD + d];
    float x1 = p[d];
    float x2 = p[d + 32];
    p[d]      = x1 * c - x2 * sn;
    p[d + 32] = x1 * sn + x2 * c;
}

// ---------------------------------------------------------------------------
// Tensor-core causal GQA attention (3xBF16 scores, 3xBF16 PV).
// Grid (qb=32, h=32), 128 threads (4 warps), warp owns 16 q-rows.
// P kept in registers (C-frag == A-frag lane layout); K/V frags via ldmatrix.
// Smem (dynamic): Ks hi/lo, Vt hi/lo — [64][36] u32 each (Q stages via Ks).
// ---------------------------------------------------------------------------
#define AST 36

__global__ __launch_bounds__(128, 3) void attn_tc_kernel()
{
    extern __shared__ unsigned smA[];
    unsigned* KsH = smA;
    unsigned* KsL = KsH + 64 * AST;
    unsigned* VtH = KsL + 64 * AST;   // [d][keypair]
    unsigned* VtL = VtH + 64 * AST;

    const int qb = blockIdx.x, h = blockIdx.y, kvh = h >> 2;
    const int t = threadIdx.x;
    const int lane = t & 31, w = t >> 5;
    const int g = lane >> 2, q = lane & 3;
    const int r0 = w * 16 + g;

    const int vD = t & 63;
    const int vR = t >> 6;

    // ldmatrix lane addressing (B-frag pattern: np pairs of n8 blocks)
    const int sel = lane >> 3, rin = lane & 7;
    const uint32_t kHb = smem_u32(KsH), kLb = smem_u32(KsL);
    const uint32_t vHb = smem_u32(VtH), vLb = smem_u32(VtL);
    uint32_t nOff[4];
#pragma unroll
    for (int np = 0; np < 4; np++)
        nOff[np] = (uint32_t)((np * 16 + (sel >> 1) * 8 + rin) * AST * 4
                              + (sel & 1) * 16);

    // ---- stage Q (scaled, split) into Ks buffers ----
#pragma unroll
    for (int j = 0; j < 8; j++) {
        int i = t + 128 * j;
        int r = i >> 4, d4 = i & 15;
        float4 v = *reinterpret_cast<const float4*>(
            &g_q[(size_t)(qb * 64 + r) * D_MODEL + h * HD + d4 * 4]);
        unsigned h0, l0, h1, l1;
        split2(v.x * 0.125f, v.y * 0.125f, h0, l0);
        split2(v.z * 0.125f, v.w * 0.125f, h1, l1);
        KsH[r * AST + d4 * 2] = h0;      KsL[r * AST + d4 * 2] = l0;
        KsH[r * AST + d4 * 2 + 1] = h1;  KsL[r * AST + d4 * 2 + 1] = l1;
    }
    __syncthreads();

    // ---- preload Q fragments (warp-own rows) ----
    unsigned qh[4][4], ql[4][4];
#pragma unroll
    for (int c8 = 0; c8 < 4; c8++) {
        qh[c8][0] = KsH[r0 * AST + c8 * 8 + q];
        qh[c8][1] = KsH[(r0 + 8) * AST + c8 * 8 + q];
        qh[c8][2] = KsH[r0 * AST + c8 * 8 + q + 4];
        qh[c8][3] = KsH[(r0 + 8) * AST + c8 * 8 + q + 4];
        ql[c8][0] = KsL[r0 * AST + c8 * 8 + q];
        ql[c8][1] = KsL[(r0 + 8) * AST + c8 * 8 + q];
        ql[c8][2] = KsL[r0 * AST + c8 * 8 + q + 4];
        ql[c8][3] = KsL[(r0 + 8) * AST + c8 * 8 + q + 4];
    }

    float m0 = -1e30f, m1 = -1e30f, l0s = 0.f, l1s = 0.f;
    float acc[8][4];
#pragma unroll
    for (int nt = 0; nt < 8; nt++)
#pragma unroll
        for (int i = 0; i < 4; i++) acc[nt][i] = 0.f;

    for (int kt = 0; kt <= qb; kt++) {
        __syncthreads();  // previous tile reads done (also guards Q staging, kt=0)
        // ---- stage K ----
#pragma unroll
        for (int j = 0; j < 8; j++) {
            int i = t + 128 * j;
            int r = i >> 4, d4 = i & 15;
            float4 v = *reinterpret_cast<const float4*>(
                &g_k[(size_t)(kt * 64 + r) * KV_DIM + kvh * HD + d4 * 4]);
            unsigned h0, l0, h1, l1;
            split2(v.x, v.y, h0, l0);
            split2(v.z, v.w, h1, l1);
            KsH[r * AST + d4 * 2] = h0;      KsL[r * AST + d4 * 2] = l0;
            KsH[r * AST + d4 * 2 + 1] = h1;  KsL[r * AST + d4 * 2 + 1] = l1;
        }
        // ---- stage V transposed: Vt[d][keypair] ----
#pragma unroll
        for (int j = 0; j < 16; j++) {
            int kp = vR + 2 * j;
            float e0 = g_v[(size_t)(kt * 64 + 2 * kp) * KV_DIM + kvh * HD + vD];
            float e1 = g_v[(size_t)(kt * 64 + 2 * kp + 1) * KV_DIM + kvh * HD + vD];
            unsigned hh, ll;
            split2(e0, e1, hh, ll);
            VtH[vD * AST + kp] = hh;  VtL[vD * AST + kp] = ll;
        }
        __syncthreads();

        // ---- scores S = Q K^T (3xBF16), K frags via ldmatrix ----
        float c[8][4];
#pragma unroll
        for (int nt = 0; nt < 8; nt++)
#pragma unroll
            for (int i = 0; i < 4; i++) c[nt][i] = 0.f;

#pragma unroll
        for (int c8 = 0; c8 < 4; c8++) {
            const uint32_t kB = c8 * 32;
#pragma unroll
            for (int np = 0; np < 4; np++) {
                unsigned bh[4], bl[4];
                ldsm4(bh[0], bh[1], bh[2], bh[3], kHb + nOff[np] + kB);
                ldsm4(bl[0], bl[1], bl[2], bl[3], kLb + nOff[np] + kB);
#pragma unroll
                for (int sub = 0; sub < 2; sub++) {
                    int nt = np * 2 + sub;
                    mma_bf16(c[nt], qh[c8][0], qh[c8][1], qh[c8][2], qh[c8][3],
                             bh[sub * 2], bh[sub * 2 + 1]);
                    mma_bf16(c[nt], ql[c8][0], ql[c8][1], ql[c8][2], ql[c8][3],
                             bh[sub * 2], bh[sub * 2 + 1]);
                    mma_bf16(c[nt], qh[c8][0], qh[c8][1], qh[c8][2], qh[c8][3],
                             bl[sub * 2], bl[sub * 2 + 1]);
                }
            }
        }

        // ---- causal mask (diagonal tile) ----
        if (kt == qb) {
#pragma unroll
            for (int nt = 0; nt < 8; nt++) {
                int k0c = nt * 8 + 2 * q;
                if (k0c     > r0)     c[nt][0] = -1e30f;
                if (k0c + 1 > r0)     c[nt][1] = -1e30f;
                if (k0c     > r0 + 8) c[nt][2] = -1e30f;
                if (k0c + 1 > r0 + 8) c[nt][3] = -1e30f;
            }
        }

        // ---- streaming softmax ----
        float tm0 = -1e30f, tm1 = -1e30f;
#pragma unroll
        for (int nt = 0; nt < 8; nt++) {
            tm0 = fmaxf(tm0, fmaxf(c[nt][0], c[nt][1]));
            tm1 = fmaxf(tm1, fmaxf(c[nt][2], c[nt][3]));
        }
        tm0 = fmaxf(tm0, __shfl_xor_sync(0xffffffffu, tm0, 1));
        tm0 = fmaxf(tm0, __shfl_xor_sync(0xffffffffu, tm0, 2));
        tm1 = fmaxf(tm1, __shfl_xor_sync(0xffffffffu, tm1, 1));
        tm1 = fmaxf(tm1, __shfl_xor_sync(0xffffffffu, tm1, 2));
        float nm0 = fmaxf(m0, tm0), nm1 = fmaxf(m1, tm1);
        float es0 = __expf(m0 - nm0), es1 = __expf(m1 - nm1);

        float ps0 = 0.f, ps1 = 0.f;
#pragma unroll
        for (int nt = 0; nt < 8; nt++) {
            c[nt][0] = __expf(c[nt][0] - nm0);
            c[nt][1] = __expf(c[nt][1] - nm0);
            c[nt][2] = __expf(c[nt][2] - nm1);
            c[nt][3] = __expf(c[nt][3] - nm1);
            ps0 += c[nt][0] + c[nt][1];
            ps1 += c[nt][2] + c[nt][3];
        }
        ps0 += __shfl_xor_sync(0xffffffffu, ps0, 1);
        ps0 += __shfl_xor_sync(0xffffffffu, ps0, 2);
        ps1 += __shfl_xor_sync(0xffffffffu, ps1, 1);
        ps1 += __shfl_xor_sync(0xffffffffu, ps1, 2);
        l0s = l0s * es0 + ps0;
        l1s = l1s * es1 + ps1;
        m0 = nm0; m1 = nm1;

#pragma unroll
        for (int nt = 0; nt < 8; nt++) {
            acc[nt][0] *= es0; acc[nt][1] *= es0;
            acc[nt][2] *= es1; acc[nt][3] *= es1;
        }

        // ---- P fragments directly from score registers ----
        unsigned ph[4][4], pl[4][4];
#pragma unroll
        for (int c8 = 0; c8 < 4; c8++) {
            split2(c[2 * c8][0],     c[2 * c8][1],     ph[c8][0], pl[c8][0]);
            split2(c[2 * c8][2],     c[2 * c8][3],     ph[c8][1], pl[c8][1]);
            split2(c[2 * c8 + 1][0], c[2 * c8 + 1][1], ph[c8][2], pl[c8][2]);
            split2(c[2 * c8 + 1][2], c[2 * c8 + 1][3], ph[c8][3], pl[c8][3]);
        }

        // ---- O += P V (3xBF16), V frags via ldmatrix ----
#pragma unroll
        for (int c8 = 0; c8 < 4; c8++) {
            const uint32_t kB = c8 * 32;
#pragma unroll
            for (int np = 0; np < 4; np++) {
                unsigned bh[4], bl[4];
                ldsm4(bh[0], bh[1], bh[2], bh[3], vHb + nOff[np] + kB);
                ldsm4(bl[0], bl[1], bl[2], bl[3], vLb + nOff[np] + kB);
#pragma unroll
                for (int sub = 0; sub < 2; sub++) {
                    int nt = np * 2 + sub;
                    mma_bf16(acc[nt], ph[c8][0], ph[c8][1], ph[c8][2], ph[c8][3],
                             bh[sub * 2], bh[sub * 2 + 1]);
                    mma_bf16(acc[nt], pl[c8][0], pl[c8][1], pl[c8][2], pl[c8][3],
                             bh[sub * 2], bh[sub * 2 + 1]);
                    mma_bf16(acc[nt], ph[c8][0], ph[c8][1], ph[c8][2], ph[c8][3],
                             bl[sub * 2], bl[sub * 2 + 1]);
                }
            }
        }
    }

    // ---- epilogue ----
    float inv0 = 1.f / l0s, inv1 = 1.f / l1s;
    float* o0 = &g_attn[(size_t)(qb * 64 + r0) * D_MODEL + h * HD];
    float* o1 = &g_attn[(size_t)(qb * 64 + r0 + 8) * D_MODEL + h * HD];
#pragma unroll
    for (int nt = 0; nt < 8; nt++) {
        *reinterpret_cast<float2*>(o0 + nt * 8 + 2 * q) =
            make_float2(acc[nt][0] * inv0, acc[nt][1] * inv0);
        *reinterpret_cast<float2*>(o1 + nt * 8 + 2 * q) =
            make_float2(acc[nt][2] * inv1, acc[nt][3] * inv1);
    }
}

// ---------------------------------------------------------------------------
extern "C" void kernel_launch(void* const* d_in, const int* in_sizes, int n_in,
                              void* d_out, int out_size)
{
    const float* x    = (const float*)d_in[0];
    const float* cosT = (const float*)d_in[1];
    const float* sinT = (const float*)d_in[2];
    // d_in[3] = mask: causal, applied analytically
    const float* wq = (const float*)d_in[4];
    const float* wk = (const float*)d_in[5];
    const float* wv = (const float*)d_in[6];
    const float* wo = (const float*)d_in[7];
    float* out = (float*)d_out;

    float *qp, *kp, *vp, *ap;
    cudaGetSymbolAddress((void**)&qp, g_q);
    cudaGetSymbolAddress((void**)&kp, g_k);
    cudaGetSymbolAddress((void**)&vp, g_v);
    cudaGetSymbolAddress((void**)&ap, g_attn);

    qkv_gemm_kernel<<<dim3(24, S_LEN / 128), 256>>>(x, wq, wk, wv);

    const int ropeTot = S_LEN * (NH + NKV) * (HD / 2);
    rope_kernel<<<(ropeTot + 255) / 256, 256>>>(cosT, sinT);

    const int attnSmem = 4 * 64 * AST * sizeof(unsigned);   // 36864
    cudaFuncSetAttribute(attn_tc_kernel, cudaFuncAttributeMaxDynamicSharedMemorySize, attnSmem);
    attn_tc_kernel<<<dim3(S_LEN / 64, NH), 128, attnSmem>>>();

    out_gemm_kernel<<<dim3(D_MODEL / 128, S_LEN / 128), 256>>>(ap, wo, out);

    const size_t outElems = (size_t)S_LEN * D_MODEL;
    const size_t kvElems = (size_t)S_LEN * KV_DIM;
    if ((size_t)out_size >= outElems + 2 * kvElems) {
        cudaMemcpyAsync(out + outElems, kp, kvElems * sizeof(float),
                        cudaMemcpyDeviceToDevice);
        cudaMemcpyAsync(out + outElems + kvElems, vp, kvElems * sizeof(float),
                        cudaMemcpyDeviceToDevice);
    }
}

// round 15
// speedup vs baseline: 6.6675x; 1.0745x over previous
#include <cuda_runtime.h>
#include <cuda_bf16.h>
#include <math.h>
#include <stdint.h>

#define S_LEN 2048
#define D_MODEL 2048
#define NH 32
#define NKV 8
#define HD 64
#define KV_DIM (NKV * HD)   // 512

// Scratch (no allocations allowed)
__device__ float g_q[S_LEN * D_MODEL];
__device__ float g_k[S_LEN * KV_DIM];
__device__ float g_v[S_LEN * KV_DIM];
// Pre-split bf16-pair (u32 = [k_odd|k_even]) operand arrays
__device__ unsigned g_xH[S_LEN * D_MODEL / 2],  g_xL[S_LEN * D_MODEL / 2];
__device__ unsigned g_aH[S_LEN * D_MODEL / 2],  g_aL[S_LEN * D_MODEL / 2];
__device__ unsigned g_wqH[D_MODEL * D_MODEL / 2], g_wqL[D_MODEL * D_MODEL / 2];
__device__ unsigned g_wkH[KV_DIM * D_MODEL / 2],  g_wkL[KV_DIM * D_MODEL / 2];
__device__ unsigned g_wvH[KV_DIM * D_MODEL / 2],  g_wvL[KV_DIM * D_MODEL / 2];
__device__ unsigned g_woH[D_MODEL * D_MODEL / 2], g_woL[D_MODEL * D_MODEL / 2];

// ---------------------------------------------------------------------------
// bf16 split helpers: x = hi + lo (≈17 effective mantissa bits).
// ---------------------------------------------------------------------------
__device__ __forceinline__ void split2(float x0, float x1, unsigned& hi, unsigned& lo)
{
    __nv_bfloat162 h = __floats2bfloat162_rn(x0, x1);
    float h0 = __low2float(h), h1 = __high2float(h);
    __nv_bfloat162 l = __floats2bfloat162_rn(x0 - h0, x1 - h1);
    hi = *reinterpret_cast<unsigned*>(&h);
    lo = *reinterpret_cast<unsigned*>(&l);
}

__device__ __forceinline__ void mma_bf16(float* c, unsigned a0, unsigned a1,
                                         unsigned a2, unsigned a3,
                                         unsigned b0, unsigned b1)
{
    asm volatile(
        "mma.sync.aligned.m16n8k16.row.col.f32.bf16.bf16.f32 "
        "{%0,%1,%2,%3},{%4,%5,%6,%7},{%8,%9},{%0,%1,%2,%3};\n"
        : "+f"(c[0]), "+f"(c[1]), "+f"(c[2]), "+f"(c[3])
        : "r"(a0), "r"(a1), "r"(a2), "r"(a3), "r"(b0), "r"(b1));
}

__device__ __forceinline__ uint32_t smem_u32(const void* p)
{
    uint32_t a;
    asm("{ .reg .u64 t; cvta.to.shared.u64 t, %1; cvt.u32.u64 %0, t; }"
        : "=r"(a) : "l"(p));
    return a;
}

__device__ __forceinline__ void ldsm4(unsigned& r0, unsigned& r1,
                                      unsigned& r2, unsigned& r3, uint32_t addr)
{
    asm volatile("ldmatrix.sync.aligned.m8n8.x4.shared.b16 {%0,%1,%2,%3}, [%4];"
                 : "=r"(r0), "=r"(r1), "=r"(r2), "=r"(r3) : "r"(addr));
}

__device__ __forceinline__ void cpa16(uint32_t dst, const unsigned* src)
{
    asm volatile("cp.async.cg.shared.global [%0], [%1], 16;"
                 :: "r"(dst), "l"(src) : "memory");
}
#define CP_COMMIT() asm volatile("cp.async.commit_group;" ::: "memory")
#define CP_WAIT(n)  asm volatile("cp.async.wait_group %0;" :: "n"(n) : "memory")

// ---------------------------------------------------------------------------
// Pre-split kernels
// ---------------------------------------------------------------------------
__global__ void split_rows_kernel(const float* __restrict__ X,
                                  unsigned* __restrict__ H, unsigned* __restrict__ L,
                                  int total_pairs)
{
    int i = blockIdx.x * blockDim.x + threadIdx.x;
    if (i >= total_pairs) return;
    float2 v = reinterpret_cast<const float2*>(X)[i];
    unsigned hh, ll;
    split2(v.x, v.y, hh, ll);
    H[i] = hh;  L[i] = ll;
}

// W[K][N] fp32 -> H/L [N][K/2] bf16-pair u32 (transposed)
__global__ void splitT_kernel(const float* __restrict__ W,
                              unsigned* __restrict__ H, unsigned* __restrict__ L,
                              int K, int N)
{
    __shared__ float tile[32][33];
    const int kt = blockIdx.x * 32, nt = blockIdx.y * 32;
    const int t = threadIdx.x;
    const int kl = t >> 5, nl = t & 31;
#pragma unroll
    for (int j = 0; j < 4; j++)
        tile[kl + 8 * j][nl] = W[(size_t)(kt + kl + 8 * j) * N + nt + nl];
    __syncthreads();
    const int n = t >> 3, p0 = t & 7;
#pragma unroll
    for (int j = 0; j < 2; j++) {
        int p = p0 + 8 * j;
        unsigned hh, ll;
        split2(tile[2 * p][n], tile[2 * p + 1][n], hh, ll);
        size_t o = (size_t)(nt + n) * (K / 2) + kt / 2 + p;
        H[o] = hh;  L[o] = ll;
    }
}

// ---------------------------------------------------------------------------
// cp.async double-buffered 3xBF16 GEMM.
// A: [M][K/2] u32 bf16-pairs (hi/lo), B: [N][K/2] (pre-transposed), C fp32.
// Block 128x128x32, 8 warps (2M x 4N), m16n8k16, frags via ldmatrix.
// ---------------------------------------------------------------------------
#define GST 20
#define ST_U32 (128 * GST)              // u32 per array per stage
#define STAGE_BYTES (4 * ST_U32 * 4)    // AH,AL,BH,BL = 40960 B
#define GEMM_SMEM (2 * STAGE_BYTES)     // 81920 B

__device__ __forceinline__ void gemm_body(
    const unsigned* __restrict__ AH, const unsigned* __restrict__ AL,
    const unsigned* __restrict__ BH, const unsigned* __restrict__ BL,
    float* __restrict__ C, int N, int K, int bx, int by)
{
    extern __shared__ unsigned smg[];
    const int tid = threadIdx.x;
    const int lane = tid & 31, wid = tid >> 5;
    const int wm = wid & 1, wn = wid >> 1;
    const int g = lane >> 2, q = lane & 3;
    const uint32_t sb = smem_u32(smg);

    const int KP = K >> 1;
    AH += (size_t)(by * 128) * KP;  AL += (size_t)(by * 128) * KP;
    BH += (size_t)(bx * 128) * KP;  BL += (size_t)(bx * 128) * KP;
    C += (size_t)by * 128 * N + (size_t)bx * 128;

    // cp.async mapping: row = tid>>1, chunks (tid&1)*2 + {0,1}  (16B chunks)
    const int sRow = tid >> 1, sC = (tid & 1) * 2;
    const uint32_t dstRow = sb + sRow * GST * 4 + sC * 16;
    const size_t srcRow = (size_t)sRow * KP + sC * 4;

    // ldmatrix offsets (validated in R12)
    const int sel = lane >> 3, rin = lane & 7;
    uint32_t aOff[4];
#pragma unroll
    for (int mt = 0; mt < 4; mt++)
        aOff[mt] = (uint32_t)((wm * 64 + mt * 16 + (sel & 1) * 8 + rin) * GST * 4
                              + (sel >> 1) * 16);
    uint32_t bOff[2];
#pragma unroll
    for (int np = 0; np < 2; np++)
        bOff[np] = (uint32_t)((wn * 32 + np * 16 + (sel >> 1) * 8 + rin) * GST * 4
                              + (sel & 1) * 16);

    float c[4][4][4];
#pragma unroll
    for (int mt = 0; mt < 4; mt++)
#pragma unroll
        for (int nt = 0; nt < 4; nt++)
#pragma unroll
            for (int i = 0; i < 4; i++) c[mt][nt][i] = 0.f;

    const int NT = K / 32;

    // stage-issue helper (8 x 16B per thread)
#define ISSUE_STAGE(buf, tile_)                                                  \
    do {                                                                         \
        uint32_t d0 = dstRow + (buf) * STAGE_BYTES;                              \
        size_t s0 = srcRow + (size_t)(tile_) * 16;                               \
        cpa16(d0,                     AH + s0);  cpa16(d0 + 16,                  AH + s0 + 4); \
        cpa16(d0 + ST_U32 * 4,        AL + s0);  cpa16(d0 + 16 + ST_U32 * 4,     AL + s0 + 4); \
        cpa16(d0 + 2 * ST_U32 * 4,    BH + s0);  cpa16(d0 + 16 + 2 * ST_U32 * 4, BH + s0 + 4); \
        cpa16(d0 + 3 * ST_U32 * 4,    BL + s0);  cpa16(d0 + 16 + 3 * ST_U32 * 4, BL + s0 + 4); \
    } while (0)

    ISSUE_STAGE(0, 0);
    CP_COMMIT();

    for (int t = 0; t < NT; t++) {
        const int buf = t & 1;
        if (t + 1 < NT) {
            ISSUE_STAGE(buf ^ 1, t + 1);
            CP_COMMIT();
            CP_WAIT(1);
        } else {
            CP_WAIT(0);
        }
        __syncthreads();

        const uint32_t aHb = sb + buf * STAGE_BYTES;
        const uint32_t aLb = aHb + ST_U32 * 4;
        const uint32_t bHb = aHb + 2 * ST_U32 * 4;
        const uint32_t bLb = aHb + 3 * ST_U32 * 4;

#pragma unroll
        for (int c8 = 0; c8 < 2; c8++) {
            const uint32_t kB = c8 * 32;
            unsigned ah[4][4], al[4][4];
#pragma unroll
            for (int mt = 0; mt < 4; mt++) {
                ldsm4(ah[mt][0], ah[mt][1], ah[mt][2], ah[mt][3], aHb + aOff[mt] + kB);
                ldsm4(al[mt][0], al[mt][1], al[mt][2], al[mt][3], aLb + aOff[mt] + kB);
            }
#pragma unroll
            for (int np = 0; np < 2; np++) {
                unsigned bh[4], bl[4];
                ldsm4(bh[0], bh[1], bh[2], bh[3], bHb + bOff[np] + kB);
                ldsm4(bl[0], bl[1], bl[2], bl[3], bLb + bOff[np] + kB);
#pragma unroll
                for (int sub = 0; sub < 2; sub++) {
                    int nt = np * 2 + sub;
#pragma unroll
                    for (int mt = 0; mt < 4; mt++) {
                        mma_bf16(c[mt][nt], ah[mt][0], ah[mt][1], ah[mt][2], ah[mt][3],
                                 bh[sub * 2], bh[sub * 2 + 1]);
                        mma_bf16(c[mt][nt], al[mt][0], al[mt][1], al[mt][2], al[mt][3],
                                 bh[sub * 2], bh[sub * 2 + 1]);
                        mma_bf16(c[mt][nt], ah[mt][0], ah[mt][1], ah[mt][2], ah[mt][3],
                                 bl[sub * 2], bl[sub * 2 + 1]);
                    }
                }
            }
        }
        __syncthreads();
    }
#undef ISSUE_STAGE

#pragma unroll
    for (int mt = 0; mt < 4; mt++) {
#pragma unroll
        for (int nt = 0; nt < 4; nt++) {
            int row = wm * 64 + mt * 16 + g;
            int col = wn * 32 + nt * 8 + q * 2;
            *reinterpret_cast<float2*>(&C[(size_t)row * N + col]) =
                make_float2(c[mt][nt][0], c[mt][nt][1]);
            *reinterpret_cast<float2*>(&C[(size_t)(row + 8) * N + col]) =
                make_float2(c[mt][nt][2], c[mt][nt][3]);
        }
    }
}

__global__ __launch_bounds__(256, 2) void qkv_gemm_kernel(
    const unsigned* __restrict__ xH, const unsigned* __restrict__ xL)
{
    int bx = blockIdx.x;
    const unsigned *BH, *BL; float* C; int N; int cx;
    if (bx < 16)      { BH = g_wqH; BL = g_wqL; C = g_q; N = D_MODEL; cx = bx; }
    else if (bx < 20) { BH = g_wkH; BL = g_wkL; C = g_k; N = KV_DIM;  cx = bx - 16; }
    else              { BH = g_wvH; BL = g_wvL; C = g_v; N = KV_DIM;  cx = bx - 20; }
    gemm_body(xH, xL, BH, BL, C, N, D_MODEL, cx, blockIdx.y);
}

__global__ __launch_bounds__(256, 2) void out_gemm_kernel(float* __restrict__ C)
{
    gemm_body(g_aH, g_aL, g_woH, g_woL, C, D_MODEL, D_MODEL, blockIdx.x, blockIdx.y);
}

// ---------------------------------------------------------------------------
// RoPE in place on g_q, g_k.
// ---------------------------------------------------------------------------
__global__ void rope_kernel(const float* __restrict__ cosT, const float* __restrict__ sinT)
{
    int idx = blockIdx.x * blockDim.x + threadIdx.x;
    const int total = S_LEN * (NH + NKV) * (HD / 2);
    if (idx >= total) return;
    int d = idx & 31;
    int row = idx >> 5;
    float* p;
    int s;
    if (row < S_LEN * NH) {
        s = row >> 5;
        int h = row & 31;
        p = g_q + (size_t)s * D_MODEL + h * HD;
    } else {
        int r = row - S_LEN * NH;
        s = r >> 3;
        int kv = r & 7;
        p = g_k + (size_t)s * KV_DIM + kv * HD;
    }
    float c = cosT[s * HD + d];
    float sn = sinT[s * HD + d];
    float x1 = p[d];
    float x2 = p[d + 32];
    p[d]      = x1 * c - x2 * sn;
    p[d + 32] = x1 * sn + x2 * c;
}

// ---------------------------------------------------------------------------
// Tensor-core causal GQA attention (3xBF16 scores, 3xBF16 PV). R12-proven.
// Epilogue now writes pre-split bf16 output (g_aH/g_aL) for the out GEMM.
// ---------------------------------------------------------------------------
#define AST 36

__global__ __launch_bounds__(128, 3) void attn_tc_kernel()
{
    extern __shared__ unsigned smA[];
    unsigned* KsH = smA;
    unsigned* KsL = KsH + 64 * AST;
    unsigned* VtH = KsL + 64 * AST;   // [d][keypair]
    unsigned* VtL = VtH + 64 * AST;

    const int qb = blockIdx.x, h = blockIdx.y, kvh = h >> 2;
    const int t = threadIdx.x;
    const int lane = t & 31, w = t >> 5;
    const int g = lane >> 2, q = lane & 3;
    const int r0 = w * 16 + g;

    const int vD = t & 63;
    const int vR = t >> 6;

    const int sel = lane >> 3, rin = lane & 7;
    const uint32_t kHb = smem_u32(KsH), kLb = smem_u32(KsL);
    const uint32_t vHb = smem_u32(VtH), vLb = smem_u32(VtL);
    uint32_t nOff[4];
#pragma unroll
    for (int np = 0; np < 4; np++)
        nOff[np] = (uint32_t)((np * 16 + (sel >> 1) * 8 + rin) * AST * 4
                              + (sel & 1) * 16);

    // ---- stage Q (scaled, split) into Ks buffers ----
#pragma unroll
    for (int j = 0; j < 8; j++) {
        int i = t + 128 * j;
        int r = i >> 4, d4 = i & 15;
        float4 v = *reinterpret_cast<const float4*>(
            &g_q[(size_t)(qb * 64 + r) * D_MODEL + h * HD + d4 * 4]);
        unsigned h0, l0, h1, l1;
        split2(v.x * 0.125f, v.y * 0.125f, h0, l0);
        split2(v.z * 0.125f, v.w * 0.125f, h1, l1);
        KsH[r * AST + d4 * 2] = h0;      KsL[r * AST + d4 * 2] = l0;
        KsH[r * AST + d4 * 2 + 1] = h1;  KsL[r * AST + d4 * 2 + 1] = l1;
    }
    __syncthreads();

    unsigned qh[4][4], ql[4][4];
#pragma unroll
    for (int c8 = 0; c8 < 4; c8++) {
        qh[c8][0] = KsH[r0 * AST + c8 * 8 + q];
        qh[c8][1] = KsH[(r0 + 8) * AST + c8 * 8 + q];
        qh[c8][2] = KsH[r0 * AST + c8 * 8 + q + 4];
        qh[c8][3] = KsH[(r0 + 8) * AST + c8 * 8 + q + 4];
        ql[c8][0] = KsL[r0 * AST + c8 * 8 + q];
        ql[c8][1] = KsL[(r0 + 8) * AST + c8 * 8 + q];
        ql[c8][2] = KsL[r0 * AST + c8 * 8 + q + 4];
        ql[c8][3] = KsL[(r0 + 8) * AST + c8 * 8 + q + 4];
    }

    float m0 = -1e30f, m1 = -1e30f, l0s = 0.f, l1s = 0.f;
    float acc[8][4];
#pragma unroll
    for (int nt = 0; nt < 8; nt++)
#pragma unroll
        for (int i = 0; i < 4; i++) acc[nt][i] = 0.f;

    for (int kt = 0; kt <= qb; kt++) {
        __syncthreads();
#pragma unroll
        for (int j = 0; j < 8; j++) {
            int i = t + 128 * j;
            int r = i >> 4, d4 = i & 15;
            float4 v = *reinterpret_cast<const float4*>(
                &g_k[(size_t)(kt * 64 + r) * KV_DIM + kvh * HD + d4 * 4]);
            unsigned h0, l0, h1, l1;
            split2(v.x, v.y, h0, l0);
            split2(v.z, v.w, h1, l1);
            KsH[r * AST + d4 * 2] = h0;      KsL[r * AST + d4 * 2] = l0;
            KsH[r * AST + d4 * 2 + 1] = h1;  KsL[r * AST + d4 * 2 + 1] = l1;
        }
#pragma unroll
        for (int j = 0; j < 16; j++) {
            int kp = vR + 2 * j;
            float e0 = g_v[(size_t)(kt * 64 + 2 * kp) * KV_DIM + kvh * HD + vD];
            float e1 = g_v[(size_t)(kt * 64 + 2 * kp + 1) * KV_DIM + kvh * HD + vD];
            unsigned hh, ll;
            split2(e0, e1, hh, ll);
            VtH[vD * AST + kp] = hh;  VtL[vD * AST + kp] = ll;
        }
        __syncthreads();

        float c[8][4];
#pragma unroll
        for (int nt = 0; nt < 8; nt++)
#pragma unroll
            for (int i = 0; i < 4; i++) c[nt][i] = 0.f;

#pragma unroll
        for (int c8 = 0; c8 < 4; c8++) {
            const uint32_t kB = c8 * 32;
#pragma unroll
            for (int np = 0; np < 4; np++) {
                unsigned bh[4], bl[4];
                ldsm4(bh[0], bh[1], bh[2], bh[3], kHb + nOff[np] + kB);
                ldsm4(bl[0], bl[1], bl[2], bl[3], kLb + nOff[np] + kB);
#pragma unroll
                for (int sub = 0; sub < 2; sub++) {
                    int nt = np * 2 + sub;
                    mma_bf16(c[nt], qh[c8][0], qh[c8][1], qh[c8][2], qh[c8][3],
                             bh[sub * 2], bh[sub * 2 + 1]);
                    mma_bf16(c[nt], ql[c8][0], ql[c8][1], ql[c8][2], ql[c8][3],
                             bh[sub * 2], bh[sub * 2 + 1]);
                    mma_bf16(c[nt], qh[c8][0], qh[c8][1], qh[c8][2], qh[c8][3],
                             bl[sub * 2], bl[sub * 2 + 1]);
                }
            }
        }

        if (kt == qb) {
#pragma unroll
            for (int nt = 0; nt < 8; nt++) {
                int k0c = nt * 8 + 2 * q;
                if (k0c     > r0)     c[nt][0] = -1e30f;
                if (k0c + 1 > r0)     c[nt][1] = -1e30f;
                if (k0c     > r0 + 8) c[nt][2] = -1e30f;
                if (k0c + 1 > r0 + 8) c[nt][3] = -1e30f;
            }
        }

        float tm0 = -1e30f, tm1 = -1e30f;
#pragma unroll
        for (int nt = 0; nt < 8; nt++) {
            tm0 = fmaxf(tm0, fmaxf(c[nt][0], c[nt][1]));
            tm1 = fmaxf(tm1, fmaxf(c[nt][2], c[nt][3]));
        }
        tm0 = fmaxf(tm0, __shfl_xor_sync(0xffffffffu, tm0, 1));
        tm0 = fmaxf(tm0, __shfl_xor_sync(0xffffffffu, tm0, 2));
        tm1 = fmaxf(tm1, __shfl_xor_sync(0xffffffffu, tm1, 1));
        tm1 = fmaxf(tm1, __shfl_xor_sync(0xffffffffu, tm1, 2));
        float nm0 = fmaxf(m0, tm0), nm1 = fmaxf(m1, tm1);
        float es0 = __expf(m0 - nm0), es1 = __expf(m1 - nm1);

        float ps0 = 0.f, ps1 = 0.f;
#pragma unroll
        for (int nt = 0; nt < 8; nt++) {
            c[nt][0] = __expf(c[nt][0] - nm0);
            c[nt][1] = __expf(c[nt][1] - nm0);
            c[nt][2] = __expf(c[nt][2] - nm1);
            c[nt][3] = __expf(c[nt][3] - nm1);
            ps0 += c[nt][0] + c[nt][1];
            ps1 += c[nt][2] + c[nt][3];
        }
        ps0 += __shfl_xor_sync(0xffffffffu, ps0, 1);
        ps0 += __shfl_xor_sync(0xffffffffu, ps0, 2);
        ps1 += __shfl_xor_sync(0xffffffffu, ps1, 1);
        ps1 += __shfl_xor_sync(0xffffffffu, ps1, 2);
        l0s = l0s * es0 + ps0;
        l1s = l1s * es1 + ps1;
        m0 = nm0; m1 = nm1;

#pragma unroll
        for (int nt = 0; nt < 8; nt++) {
            acc[nt][0] *= es0; acc[nt][1] *= es0;
            acc[nt][2] *= es1; acc[nt][3] *= es1;
        }

        // P fragments directly from score registers
        unsigned ph[4][4], pl[4][4];
#pragma unroll
        for (int c8 = 0; c8 < 4; c8++) {
            split2(c[2 * c8][0],     c[2 * c8][1],     ph[c8][0], pl[c8][0]);
            split2(c[2 * c8][2],     c[2 * c8][3],     ph[c8][1], pl[c8][1]);
            split2(c[2 * c8 + 1][0], c[2 * c8 + 1][1], ph[c8][2], pl[c8][2]);
            split2(c[2 * c8 + 1][2], c[2 * c8 + 1][3], ph[c8][3], pl[c8][3]);
        }

#pragma unroll
        for (int c8 = 0; c8 < 4; c8++) {
            const uint32_t kB = c8 * 32;
#pragma unroll
            for (int np = 0; np < 4; np++) {
                unsigned bh[4], bl[4];
                ldsm4(bh[0], bh[1], bh[2], bh[3], vHb + nOff[np] + kB);
                ldsm4(bl[0], bl[1], bl[2], bl[3], vLb + nOff[np] + kB);
#pragma unroll
                for (int sub = 0; sub < 2; sub++) {
                    int nt = np * 2 + sub;
                    mma_bf16(acc[nt], ph[c8][0], ph[c8][1], ph[c8][2], ph[c8][3],
                             bh[sub * 2], bh[sub * 2 + 1]);
                    mma_bf16(acc[nt], pl[c8][0], pl[c8][1], pl[c8][2], pl[c8][3],
                             bh[sub * 2], bh[sub * 2 + 1]);
                    mma_bf16(acc[nt], ph[c8][0], ph[c8][1], ph[c8][2], ph[c8][3],
                             bl[sub * 2], bl[sub * 2 + 1]);
                }
            }
        }
    }

    // ---- epilogue: write pre-split bf16 output for the out GEMM ----
    float inv0 = 1.f / l0s, inv1 = 1.f / l1s;
    const size_t rowU0 = ((size_t)(qb * 64 + r0) * D_MODEL + h * HD) >> 1;
    const size_t rowU1 = ((size_t)(qb * 64 + r0 + 8) * D_MODEL + h * HD) >> 1;
#pragma unroll
    for (int nt = 0; nt < 8; nt++) {
        unsigned hh, ll;
        split2(acc[nt][0] * inv0, acc[nt][1] * inv0, hh, ll);
        g_aH[rowU0 + nt * 4 + q] = hh;
        g_aL[rowU0 + nt * 4 + q] = ll;
        split2(acc[nt][2] * inv1, acc[nt][3] * inv1, hh, ll);
        g_aH[rowU1 + nt * 4 + q] = hh;
        g_aL[rowU1 + nt * 4 + q] = ll;
    }
}

// ---------------------------------------------------------------------------
extern "C" void kernel_launch(void* const* d_in, const int* in_sizes, int n_in,
                              void* d_out, int out_size)
{
    const float* x    = (const float*)d_in[0];
    const float* cosT = (const float*)d_in[1];
    const float* sinT = (const float*)d_in[2];
    // d_in[3] = mask: causal, applied analytically
    const float* wq = (const float*)d_in[4];
    const float* wk = (const float*)d_in[5];
    const float* wv = (const float*)d_in[6];
    const float* wo = (const float*)d_in[7];
    float* out = (float*)d_out;

    float *kp, *vp;
    unsigned *xH, *xL, *wqH, *wqL, *wkH, *wkL, *wvH, *wvL, *woH, *woL;
    cudaGetSymbolAddress((void**)&kp, g_k);
    cudaGetSymbolAddress((void**)&vp, g_v);
    cudaGetSymbolAddress((void**)&xH, g_xH);   cudaGetSymbolAddress((void**)&xL, g_xL);
    cudaGetSymbolAddress((void**)&wqH, g_wqH); cudaGetSymbolAddress((void**)&wqL, g_wqL);
    cudaGetSymbolAddress((void**)&wkH, g_wkH); cudaGetSymbolAddress((void**)&wkL, g_wkL);
    cudaGetSymbolAddress((void**)&wvH, g_wvH); cudaGetSymbolAddress((void**)&wvL, g_wvL);
    cudaGetSymbolAddress((void**)&woH, g_woH); cudaGetSymbolAddress((void**)&woL, g_woL);

    // Pre-split operands
    const int xPairs = S_LEN * D_MODEL / 2;
    split_rows_kernel<<<(xPairs + 255) / 256, 256>>>(x, xH, xL, xPairs);
    splitT_kernel<<<dim3(D_MODEL / 32, D_MODEL / 32), 256>>>(wq, wqH, wqL, D_MODEL, D_MODEL);
    splitT_kernel<<<dim3(D_MODEL / 32, KV_DIM / 32), 256>>>(wk, wkH, wkL, D_MODEL, KV_DIM);
    splitT_kernel<<<dim3(D_MODEL / 32, KV_DIM / 32), 256>>>(wv, wvH, wvL, D_MODEL, KV_DIM);
    splitT_kernel<<<dim3(D_MODEL / 32, D_MODEL / 32), 256>>>(wo, woH, woL, D_MODEL, D_MODEL);

    cudaFuncSetAttribute(qkv_gemm_kernel, cudaFuncAttributeMaxDynamicSharedMemorySize, GEMM_SMEM);
    cudaFuncSetAttribute(out_gemm_kernel, cudaFuncAttributeMaxDynamicSharedMemorySize, GEMM_SMEM);

    qkv_gemm_kernel<<<dim3(24, S_LEN / 128), 256, GEMM_SMEM>>>(xH, xL);

    const int ropeTot = S_LEN * (NH + NKV) * (HD / 2);
    rope_kernel<<<(ropeTot + 255) / 256, 256>>>(cosT, sinT);

    const int attnSmem = 4 * 64 * AST * sizeof(unsigned);   // 36864
    cudaFuncSetAttribute(attn_tc_kernel, cudaFuncAttributeMaxDynamicSharedMemorySize, attnSmem);
    attn_tc_kernel<<<dim3(S_LEN / 64, NH), 128, attnSmem>>>();

    out_gemm_kernel<<<dim3(D_MODEL / 128, S_LEN / 128), 256, GEMM_SMEM>>>(out);

    const size_t outElems = (size_t)S_LEN * D_MODEL;
    const size_t kvElems = (size_t)S_LEN * KV_DIM;
    if ((size_t)out_size >= outElems + 2 * kvElems) {
        cudaMemcpyAsync(out + outElems, kp, kvElems * sizeof(float),
                        cudaMemcpyDeviceToDevice);
        cudaMemcpyAsync(out + outElems + kvElems, vp, kvElems * sizeof(float),
                        cudaMemcpyDeviceToDevice);
    }
}